// round 7
// baseline (speedup 1.0000x reference)
// FSAS_V5 fused forward — one CTA per 8x8 patch, 1024 threads (32 warps).
// Expand + projection GEMMs on mma.sync bf16 hi/lo split (≈ fp32 accuracy).
// R7 fix: dw-weight load is a strided loop again (1152 elems > 1024 threads).
#include <cuda_runtime.h>
#include <cuda_bf16.h>
#include <cstdint>

#define HH 256
#define WW 256
#define EPSF 1e-6f
#define L2T_OVER_32 0.41524101186092030f

// ---- dynamic smem layout (float offsets) ----
#define OFF_QKV  0                 // 384 * 65 fp32
#define OFF_HID  24960             // 128 * 101 fp32 hidden chunk
#define OFF_CORR OFF_HID           // 128 * 65 overlay (phase 4+)
#define OFF_G    37888             // g_norm[128], g_qnorm[128], g_knorm[128]
#define OFF_SC   38272             // sincos table: cos[512], sin[512]
#define OFF_DW   39296             // 128*9 dw weights (per chunk)
#define OFF_RQ   40448
#define OFF_RK   40512
#define OFF_RN   40576
#define ARENA_F  40640             // bf16 tile arena @ byte 162,560
// phase-1 arena (rows strided 144 B -> ldmatrix conflict-free)
#define XHI 0
#define XLO 14976
#define WHI 29952
#define WLO 48384
// proj arena (rows strided 272 B)
#define WPH 0
#define WPL 17408
#define CBH 34816
#define CBL 52224
#define ARENA_BYTES 69632
#define SMEM_BYTES (ARENA_F * 4 + ARENA_BYTES)   // 232,192 B

__device__ __forceinline__ uint32_t smem_u32(const void* p) {
    uint32_t a;
    asm("{ .reg .u64 t; cvta.to.shared.u64 t, %1; cvt.u32.u64 %0, t; }"
        : "=r"(a) : "l"(p));
    return a;
}
__device__ __forceinline__ void ldsm4(uint32_t* r, uint32_t addr) {
    asm volatile("ldmatrix.sync.aligned.m8n8.x4.shared.b16 {%0,%1,%2,%3}, [%4];"
                 : "=r"(r[0]), "=r"(r[1]), "=r"(r[2]), "=r"(r[3]) : "r"(addr));
}
__device__ __forceinline__ void ldsm2(uint32_t& r0, uint32_t& r1, uint32_t addr) {
    asm volatile("ldmatrix.sync.aligned.m8n8.x2.shared.b16 {%0,%1}, [%2];"
                 : "=r"(r0), "=r"(r1) : "r"(addr));
}
__device__ __forceinline__ void mma16816(float* c, const uint32_t* a,
                                         uint32_t b0, uint32_t b1) {
    asm volatile("mma.sync.aligned.m16n8k16.row.col.f32.bf16.bf16.f32 "
                 "{%0,%1,%2,%3}, {%4,%5,%6,%7}, {%8,%9}, {%0,%1,%2,%3};"
                 : "+f"(c[0]), "+f"(c[1]), "+f"(c[2]), "+f"(c[3])
                 : "r"(a[0]), "r"(a[1]), "r"(a[2]), "r"(a[3]), "r"(b0), "r"(b1));
}
__device__ __forceinline__ uint32_t pack_hi_lo(float v0, float v1, uint32_t& lo) {
    __nv_bfloat16 h0 = __float2bfloat16(v0);
    __nv_bfloat16 h1 = __float2bfloat16(v1);
    __nv_bfloat16 l0 = __float2bfloat16(v0 - __bfloat162float(h0));
    __nv_bfloat16 l1 = __float2bfloat16(v1 - __bfloat162float(h1));
    lo = ((uint32_t)__bfloat16_as_ushort(l1) << 16) | __bfloat16_as_ushort(l0);
    return ((uint32_t)__bfloat16_as_ushort(h1) << 16) | __bfloat16_as_ushort(h0);
}

__global__ __launch_bounds__(1024, 1)
void fsas_fused_kernel(const float* __restrict__ x,
                       const float* __restrict__ w_hidden,
                       const float* __restrict__ w_dw,
                       const float* __restrict__ w_proj,
                       const float* __restrict__ g_norm,
                       const float* __restrict__ g_qnorm,
                       const float* __restrict__ g_knorm,
                       float* __restrict__ out)
{
    extern __shared__ float sm[];
    const int tid  = threadIdx.x;
    const int lane = tid & 31;
    const int warp = tid >> 5;
    const int px = blockIdx.x, py = blockIdx.y, b = blockIdx.z;
    const int gx0 = px * 8, gy0 = py * 8;

    char* smc = (char*)sm;
    const uint32_t sbase = smem_u32(sm);
    const uint32_t arena = sbase + ARENA_F * 4;

    // ---- phase 0: x halo -> bf16 hi/lo Xt tiles; sincos table; g tables ----
    const float* xb = x + (size_t)b * 64 * HH * WW;
    for (int idx = tid; idx < 104 * 32; idx += 1024) {
        int pos = idx >> 5, cp = idx & 31;
        float x0 = 0.f, x1 = 0.f;
        if (pos < 100) {
            int Y = pos / 10, X = pos - Y * 10;
            int gy = gy0 - 1 + Y, gx = gx0 - 1 + X;
            if ((unsigned)gy < HH && (unsigned)gx < WW) {
                size_t base = (size_t)(2 * cp) * (HH * WW) + gy * WW + gx;
                x0 = __ldg(xb + base);
                x1 = __ldg(xb + base + (size_t)(HH * WW));
            }
        }
        uint32_t lp, hp = pack_hi_lo(x0, x1, lp);
        uint32_t off = (uint32_t)(pos * 144 + cp * 4);
        *(uint32_t*)(smc + ARENA_F * 4 + XHI + off) = hp;
        *(uint32_t*)(smc + ARENA_F * 4 + XLO + off) = lp;
    }
    if (tid < 512) {                   // sincos table: (flag, m, d)
        int flag = tid >> 8, mm = (tid >> 3) & 31, d = tid & 7;
        float pos = (float)((flag ? gx0 : gy0) + d);
        float inv = exp2f(-L2T_OVER_32 * (float)mm);
        float sn, cs;
        sincosf(pos * inv, &sn, &cs);
        sm[OFF_SC + flag * 256 + mm * 8 + d]       = cs;
        sm[OFF_SC + 512 + flag * 256 + mm * 8 + d] = sn;
    } else if (tid < 896) {            // g tables
        int i = tid - 512;
        float v = (i < 128) ? __ldg(g_norm + i)
                : (i < 256) ? __ldg(g_qnorm + i - 128)
                            : __ldg(g_knorm + i - 256);
        sm[OFF_G + i] = v;
    }
    __syncthreads();

    // ============ phase 1: expand (HMMA) + depthwise 3x3, 3 chunks of 128 ============
    for (int c = 0; c < 3; ++c) {
        for (int idx = tid; idx < 128 * 32; idx += 1024) {
            int r = idx >> 5, cp = idx & 31;
            float2 wv = *(const float2*)(w_hidden + (size_t)(c * 128 + r) * 64 + 2 * cp);
            uint32_t lp, hp = pack_hi_lo(wv.x, wv.y, lp);
            uint32_t off = (uint32_t)(r * 144 + cp * 4);
            *(uint32_t*)(smc + ARENA_F * 4 + WHI + off) = hp;
            *(uint32_t*)(smc + ARENA_F * 4 + WLO + off) = lp;
        }
        for (int idx = tid; idx < 128 * 9; idx += 1024)   // R7 FIX: 1152 > 1024
            sm[OFF_DW + idx] = __ldg(w_dw + c * 128 * 9 + idx);
        __syncthreads();

        // HMMA: D[128 o][104 pos] = W @ Xt^T.  32 warps = 8 mtiles x 4 ngroups
        {
            const int mtile = warp & 7, ngroup = warp >> 3;
            const int nt0 = (ngroup == 0) ? 0 : 3 * ngroup + 1;
            const int nt1 = nt0 + ((ngroup == 0) ? 4 : 3);
            const uint32_t aHi = arena + WHI + (mtile * 16 + (lane & 15)) * 144
                                 + (lane >> 4) * 16;
            const uint32_t aLo = aHi + (WLO - WHI);
            uint32_t ahi[4][4], alo[4][4];
            #pragma unroll
            for (int ks = 0; ks < 4; ++ks) {
                ldsm4(ahi[ks], aHi + ks * 32);
                ldsm4(alo[ks], aLo + ks * 32);
            }
            for (int nt = nt0; nt < nt1; ++nt) {
                float acc[4] = {0.f, 0.f, 0.f, 0.f};
                const uint32_t bHi = arena + XHI + (nt * 8 + (lane & 7)) * 144
                                     + ((lane >> 3) & 1) * 16;
                const uint32_t bLo = bHi + (XLO - XHI);
                #pragma unroll
                for (int ks = 0; ks < 4; ++ks) {
                    uint32_t bh0, bh1, bl0, bl1;
                    ldsm2(bh0, bh1, bHi + ks * 32);
                    ldsm2(bl0, bl1, bLo + ks * 32);
                    mma16816(acc, ahi[ks], bh0, bh1);
                    mma16816(acc, ahi[ks], bl0, bl1);
                    mma16816(acc, alo[ks], bh0, bh1);
                }
                int o = mtile * 16 + (lane >> 2);
                int p = nt * 8 + 2 * (lane & 3);
                if (p < 100) {
                    sm[OFF_HID + o * 101 + p]       = acc[0];
                    sm[OFF_HID + (o + 8) * 101 + p] = acc[2];
                }
                if (p + 1 < 100) {
                    sm[OFF_HID + o * 101 + p + 1]       = acc[1];
                    sm[OFF_HID + (o + 8) * 101 + p + 1] = acc[3];
                }
            }
        }
        __syncthreads();

        // depthwise 3x3: thread = (channel, 1 output row)
        {
            int ch = tid & 127, rr = tid >> 7;
            const float* wd = &sm[OFF_DW + ch * 9];
            float w0 = wd[0], w1 = wd[1], w2 = wd[2], w3 = wd[3], w4 = wd[4],
                  w5 = wd[5], w6 = wd[6], w7 = wd[7], w8 = wd[8];
            const float* hb = &sm[OFF_HID + ch * 101];
            float r0[10], r1[10], r2[10];
            #pragma unroll
            for (int xx = 0; xx < 10; ++xx) {
                r0[xx] = hb[rr * 10 + xx];
                r1[xx] = hb[(rr + 1) * 10 + xx];
                r2[xx] = hb[(rr + 2) * 10 + xx];
            }
            #pragma unroll
            for (int xx = 0; xx < 8; ++xx) {
                float s = w0 * r0[xx];
                s = fmaf(w1, r0[xx + 1], s); s = fmaf(w2, r0[xx + 2], s);
                s = fmaf(w3, r1[xx], s);     s = fmaf(w4, r1[xx + 1], s);
                s = fmaf(w5, r1[xx + 2], s); s = fmaf(w6, r2[xx], s);
                s = fmaf(w7, r2[xx + 1], s); s = fmaf(w8, r2[xx + 2], s);
                sm[OFF_QKV + (c * 128 + ch) * 65 + rr * 8 + xx] = s;
            }
        }
        __syncthreads();
    }

    // ---- phase 2: RMS factors for q and k (warp -> 2 pixels) ----
    #pragma unroll
    for (int pi = 0; pi < 2; ++pi) {
        int pix = warp * 2 + pi;
        float sq = 0.f, sk = 0.f;
        #pragma unroll
        for (int r = 0; r < 4; ++r) {
            int cc = lane + r * 32;
            float qv = sm[OFF_QKV + cc * 65 + pix];
            float kv = sm[OFF_QKV + (128 + cc) * 65 + pix];
            sq = fmaf(qv, qv, sq);
            sk = fmaf(kv, kv, sk);
        }
        #pragma unroll
        for (int off = 16; off; off >>= 1) {
            sq += __shfl_xor_sync(0xffffffffu, sq, off);
            sk += __shfl_xor_sync(0xffffffffu, sk, off);
        }
        if (lane == 0) {
            sm[OFF_RQ + pix] = rsqrtf(sq * (1.f / 128.f) + EPSF);
            sm[OFF_RK + pix] = rsqrtf(sk * (1.f / 128.f) + EPSF);
        }
    }
    __syncthreads();

    // ---- phase 3: RMSNorm scale + 2D RoPE (table-driven, g from smem) ----
    for (int idx = tid; idx < 64 * 64; idx += 1024) {
        int m = idx >> 6, pix = idx & 63;
        int flag = (m >> 5), mm = m & 31;
        int d = flag ? (pix & 7) : (pix >> 3);
        float cs = sm[OFF_SC + flag * 256 + mm * 8 + d];
        float sn = sm[OFF_SC + 512 + flag * 256 + mm * 8 + d];
        int c0 = 2 * m;
        float rqp = sm[OFF_RQ + pix], rkp = sm[OFF_RK + pix];
        float gq0 = sm[OFF_G + 128 + c0], gq1 = sm[OFF_G + 129 + c0];
        float gk0 = sm[OFF_G + 256 + c0], gk1 = sm[OFF_G + 257 + c0];

        float q0 = sm[OFF_QKV + c0 * 65 + pix]       * rqp * gq0;
        float q1 = sm[OFF_QKV + (c0 + 1) * 65 + pix] * rqp * gq1;
        sm[OFF_QKV + c0 * 65 + pix]       = q0 * cs - q1 * sn;
        sm[OFF_QKV + (c0 + 1) * 65 + pix] = q1 * cs + q0 * sn;

        float k0 = sm[OFF_QKV + (128 + c0) * 65 + pix] * rkp * gk0;
        float k1 = sm[OFF_QKV + (129 + c0) * 65 + pix] * rkp * gk1;
        sm[OFF_QKV + (128 + c0) * 65 + pix] = k0 * cs - k1 * sn;
        sm[OFF_QKV + (129 + c0) * 65 + pix] = k1 * cs + k0 * sn;
    }

    // ---- phase 3.5: w_proj -> bf16 hi/lo tiles [o(64)][k(128)] stride 272 ----
    #pragma unroll
    for (int t = 0; t < 4; ++t) {
        int idx = tid + t * 1024;
        int o = idx >> 6, kp = idx & 63;
        float2 wv = __ldg((const float2*)w_proj + idx);
        uint32_t lp, hp = pack_hi_lo(wv.x, wv.y, lp);
        *(uint32_t*)(smc + ARENA_F * 4 + WPH + o * 272 + kp * 4) = hp;
        *(uint32_t*)(smc + ARENA_F * 4 + WPL + o * 272 + kp * 4) = lp;
    }
    __syncthreads();

    // ---- phase 4: 8x8 circular conv, thread = (channel, 1 output row) ----
    {
        int cc = tid & 127, a = tid >> 7;
        const float* qb = &sm[OFF_QKV + cc * 65];
        const float* kb = &sm[OFF_QKV + (128 + cc) * 65];
        float acc[8] = {};
        #pragma unroll
        for (int i = 0; i < 8; ++i) {
            int krow = (a - i) & 7;   // uniform within warp
            float qv[8], kv[8];
            #pragma unroll
            for (int j = 0; j < 8; ++j) {
                qv[j] = qb[i * 8 + j];
                kv[j] = kb[krow * 8 + j];
            }
            #pragma unroll
            for (int j = 0; j < 8; ++j)
                #pragma unroll
                for (int bb = 0; bb < 8; ++bb)
                    acc[bb] = fmaf(qv[j], kv[(bb - j) & 7], acc[bb]);
        }
        #pragma unroll
        for (int bb = 0; bb < 8; ++bb)
            sm[OFF_CORR + cc * 65 + a * 8 + bb] = acc[bb];
    }
    __syncthreads();

    // ---- phase 5: corr RMS factor (warp -> 2 pixels) ----
    #pragma unroll
    for (int pi = 0; pi < 2; ++pi) {
        int pix = warp * 2 + pi;
        float sc = 0.f;
        #pragma unroll
        for (int r = 0; r < 4; ++r) {
            float cv = sm[OFF_CORR + (lane + r * 32) * 65 + pix];
            sc = fmaf(cv, cv, sc);
        }
        #pragma unroll
        for (int off = 16; off; off >>= 1)
            sc += __shfl_xor_sync(0xffffffffu, sc, off);
        if (lane == 0)
            sm[OFF_RN + pix] = rsqrtf(sc * (1.f / 128.f) + EPSF);
    }
    __syncthreads();

    // ---- phase 6: (v * g_norm * rn * corr) -> bf16 hi/lo B tiles [pix][k] ----
    for (int idx = tid; idx < 64 * 64; idx += 1024) {
        int pix = idx >> 6, kp = idx & 63;
        int k0 = 2 * kp;
        float rnp = sm[OFF_RN + pix];
        float c0v = sm[OFF_CORR + k0 * 65 + pix];
        float c1v = sm[OFF_CORR + (k0 + 1) * 65 + pix];
        float v0  = sm[OFF_QKV + (256 + k0) * 65 + pix];
        float v1  = sm[OFF_QKV + (257 + k0) * 65 + pix];
        float w0 = v0 * c0v * rnp * sm[OFF_G + k0];
        float w1 = v1 * c1v * rnp * sm[OFF_G + k0 + 1];
        uint32_t lp, hp = pack_hi_lo(w0, w1, lp);
        *(uint32_t*)(smc + ARENA_F * 4 + CBH + pix * 272 + kp * 4) = hp;
        *(uint32_t*)(smc + ARENA_F * 4 + CBL + pix * 272 + kp * 4) = lp;
    }
    __syncthreads();

    // ---- phase 7: projection HMMA (warps 0-15): out[64 o][64 pix] ----
    if (warp < 16) {
        const int mtile = warp & 3;
        const int ntbase = (warp >> 2) * 2;
        const uint32_t aH = arena + WPH + (mtile * 16 + (lane & 15)) * 272
                            + (lane >> 4) * 16;
        const uint32_t aL = aH + (WPL - WPH);
        uint32_t bAddr0 = arena + CBH + ((ntbase + 0) * 8 + (lane & 7)) * 272
                          + ((lane >> 3) & 1) * 16;
        uint32_t bAddr1 = bAddr0 + 8 * 272;
        float acc[2][4] = {};
        #pragma unroll
        for (int ks = 0; ks < 8; ++ks) {
            uint32_t ahi[4], alo[4];
            ldsm4(ahi, aH + ks * 32);
            ldsm4(alo, aL + ks * 32);
            #pragma unroll
            for (int t = 0; t < 2; ++t) {
                uint32_t bA = (t ? bAddr1 : bAddr0) + ks * 32;
                uint32_t bh0, bh1, bl0, bl1;
                ldsm2(bh0, bh1, bA);
                ldsm2(bl0, bl1, bA + (CBL - CBH));
                mma16816(acc[t], ahi, bh0, bh1);
                mma16816(acc[t], ahi, bl0, bl1);
                mma16816(acc[t], alo, bh0, bh1);
            }
        }
        float* ob = out + (size_t)b * 64 * HH * WW;
        int o = mtile * 16 + (lane >> 2);
        int gxp = gx0 + 2 * (lane & 3);
        #pragma unroll
        for (int t = 0; t < 2; ++t) {
            int gy = gy0 + ntbase + t;
            float2 r0 = make_float2(acc[t][0], acc[t][1]);
            float2 r1 = make_float2(acc[t][2], acc[t][3]);
            *(float2*)(ob + (size_t)o * (HH * WW) + gy * WW + gxp)       = r0;
            *(float2*)(ob + (size_t)(o + 8) * (HH * WW) + gy * WW + gxp) = r1;
        }
    }
}

extern "C" void kernel_launch(void* const* d_in, const int* in_sizes, int n_in,
                              void* d_out, int out_size)
{
    (void)in_sizes; (void)n_in; (void)out_size;
    const float* x        = (const float*)d_in[0];
    const float* w_hidden = (const float*)d_in[1];
    const float* w_dw     = (const float*)d_in[2];
    const float* w_proj   = (const float*)d_in[3];
    const float* g_norm   = (const float*)d_in[4];
    const float* g_qnorm  = (const float*)d_in[5];
    const float* g_knorm  = (const float*)d_in[6];
    float* out = (float*)d_out;

    cudaFuncSetAttribute(fsas_fused_kernel,
                         cudaFuncAttributeMaxDynamicSharedMemorySize, SMEM_BYTES);

    dim3 grid(WW / 8, HH / 8, 4);
    fsas_fused_kernel<<<grid, 1024, SMEM_BYTES>>>(
        x, w_hidden, w_dw, w_proj, g_norm, g_qnorm, g_knorm, out);
}

// round 8
// speedup vs baseline: 1.0350x; 1.0350x over previous
// FSAS_V5 fused forward — one CTA per 8x8 patch, 512 threads.
// R8: SMEM-byte-cut round. Expand 4m x 4n HMMA w/ cached A-frags; proj 8-warp
// HMMA; circ conv 4 rows/thread; dw conv column-split rolling window.
#include <cuda_runtime.h>
#include <cuda_bf16.h>
#include <cstdint>

#define HH 256
#define WW 256
#define EPSF 1e-6f
#define L2T_OVER_32 0.41524101186092030f

// ---- dynamic smem layout (float offsets) ----
#define OFF_QKV  0                 // 384 * 65 fp32
#define OFF_HID  24960             // 128 * 101 fp32 hidden chunk
#define OFF_CORR OFF_HID           // 128 * 65 overlay (phase 4+)
#define OFF_G    37888             // g_norm[128], g_qnorm[128], g_knorm[128]
#define OFF_SC   38272             // sincos table: cos[512], sin[512]
#define OFF_DW   39296             // 128*9 dw weights (per chunk)
#define OFF_RQ   40448
#define OFF_RK   40512
#define OFF_RN   40576
#define ARENA_F  40640             // bf16 tile arena @ byte 162,560
// phase-1 arena (rows strided 144 B -> ldmatrix conflict-free)
#define XHI 0
#define XLO 14976
#define WHI 29952
#define WLO 48384
// proj arena (rows strided 272 B)
#define WPH 0
#define WPL 17408
#define CBH 34816
#define CBL 52224
#define ARENA_BYTES 69632
#define SMEM_BYTES (ARENA_F * 4 + ARENA_BYTES)   // 232,192 B

__device__ __forceinline__ uint32_t smem_u32(const void* p) {
    uint32_t a;
    asm("{ .reg .u64 t; cvta.to.shared.u64 t, %1; cvt.u32.u64 %0, t; }"
        : "=r"(a) : "l"(p));
    return a;
}
__device__ __forceinline__ void ldsm4(uint32_t* r, uint32_t addr) {
    asm volatile("ldmatrix.sync.aligned.m8n8.x4.shared.b16 {%0,%1,%2,%3}, [%4];"
                 : "=r"(r[0]), "=r"(r[1]), "=r"(r[2]), "=r"(r[3]) : "r"(addr));
}
__device__ __forceinline__ void ldsm2(uint32_t& r0, uint32_t& r1, uint32_t addr) {
    asm volatile("ldmatrix.sync.aligned.m8n8.x2.shared.b16 {%0,%1}, [%2];"
                 : "=r"(r0), "=r"(r1) : "r"(addr));
}
__device__ __forceinline__ void mma16816(float* c, const uint32_t* a,
                                         uint32_t b0, uint32_t b1) {
    asm volatile("mma.sync.aligned.m16n8k16.row.col.f32.bf16.bf16.f32 "
                 "{%0,%1,%2,%3}, {%4,%5,%6,%7}, {%8,%9}, {%0,%1,%2,%3};"
                 : "+f"(c[0]), "+f"(c[1]), "+f"(c[2]), "+f"(c[3])
                 : "r"(a[0]), "r"(a[1]), "r"(a[2]), "r"(a[3]), "r"(b0), "r"(b1));
}
__device__ __forceinline__ uint32_t pack_hi_lo(float v0, float v1, uint32_t& lo) {
    __nv_bfloat16 h0 = __float2bfloat16(v0);
    __nv_bfloat16 h1 = __float2bfloat16(v1);
    __nv_bfloat16 l0 = __float2bfloat16(v0 - __bfloat162float(h0));
    __nv_bfloat16 l1 = __float2bfloat16(v1 - __bfloat162float(h1));
    lo = ((uint32_t)__bfloat16_as_ushort(l1) << 16) | __bfloat16_as_ushort(l0);
    return ((uint32_t)__bfloat16_as_ushort(h1) << 16) | __bfloat16_as_ushort(h0);
}

__global__ __launch_bounds__(512, 1)
void fsas_fused_kernel(const float* __restrict__ x,
                       const float* __restrict__ w_hidden,
                       const float* __restrict__ w_dw,
                       const float* __restrict__ w_proj,
                       const float* __restrict__ g_norm,
                       const float* __restrict__ g_qnorm,
                       const float* __restrict__ g_knorm,
                       float* __restrict__ out)
{
    extern __shared__ float sm[];
    const int tid  = threadIdx.x;
    const int lane = tid & 31;
    const int warp = tid >> 5;
    const int px = blockIdx.x, py = blockIdx.y, b = blockIdx.z;
    const int gx0 = px * 8, gy0 = py * 8;

    char* smc = (char*)sm;
    const uint32_t sbase = smem_u32(sm);
    const uint32_t arena = sbase + ARENA_F * 4;

    // ---- phase 0: x halo -> bf16 hi/lo Xt tiles; sincos table; g tables ----
    const float* xb = x + (size_t)b * 64 * HH * WW;
    for (int idx = tid; idx < 104 * 32; idx += 512) {
        int pos = idx >> 5, cp = idx & 31;
        float x0 = 0.f, x1 = 0.f;
        if (pos < 100) {
            int Y = pos / 10, X = pos - Y * 10;
            int gy = gy0 - 1 + Y, gx = gx0 - 1 + X;
            if ((unsigned)gy < HH && (unsigned)gx < WW) {
                size_t base = (size_t)(2 * cp) * (HH * WW) + gy * WW + gx;
                x0 = __ldg(xb + base);
                x1 = __ldg(xb + base + (size_t)(HH * WW));
            }
        }
        uint32_t lp, hp = pack_hi_lo(x0, x1, lp);
        uint32_t off = (uint32_t)(pos * 144 + cp * 4);
        *(uint32_t*)(smc + ARENA_F * 4 + XHI + off) = hp;
        *(uint32_t*)(smc + ARENA_F * 4 + XLO + off) = lp;
    }
    {   // sincos table (all 512 threads)
        int flag = tid >> 8, mm = (tid >> 3) & 31, d = tid & 7;
        float pos = (float)((flag ? gx0 : gy0) + d);
        float inv = exp2f(-L2T_OVER_32 * (float)mm);
        float sn, cs;
        sincosf(pos * inv, &sn, &cs);
        sm[OFF_SC + flag * 256 + mm * 8 + d]       = cs;
        sm[OFF_SC + 512 + flag * 256 + mm * 8 + d] = sn;
    }
    if (tid < 384) {
        float v = (tid < 128) ? __ldg(g_norm + tid)
                : (tid < 256) ? __ldg(g_qnorm + tid - 128)
                              : __ldg(g_knorm + tid - 256);
        sm[OFF_G + tid] = v;
    }
    __syncthreads();

    // ============ phase 1: expand (HMMA 4m x 4n) + depthwise, 3 chunks ============
    for (int c = 0; c < 3; ++c) {
        for (int idx = tid; idx < 128 * 32; idx += 512) {
            int r = idx >> 5, cp = idx & 31;
            float2 wv = *(const float2*)(w_hidden + (size_t)(c * 128 + r) * 64 + 2 * cp);
            uint32_t lp, hp = pack_hi_lo(wv.x, wv.y, lp);
            uint32_t off = (uint32_t)(r * 144 + cp * 4);
            *(uint32_t*)(smc + ARENA_F * 4 + WHI + off) = hp;
            *(uint32_t*)(smc + ARENA_F * 4 + WLO + off) = lp;
        }
        for (int idx = tid; idx < 128 * 9; idx += 512)
            sm[OFF_DW + idx] = __ldg(w_dw + c * 128 * 9 + idx);
        __syncthreads();

        // HMMA: warp = (mg: 32 o-rows) x (ng: nt range). A-frags cached in regs.
        {
            const int mg = warp & 3, ng = warp >> 2;
            const int nt0 = (ng == 0) ? 0 : 3 * ng + 1;
            const int cnt = (ng == 0) ? 4 : 3;
            uint32_t ahi[2][4][4], alo[2][4][4];
            #pragma unroll
            for (int mt = 0; mt < 2; ++mt) {
                uint32_t aH = arena + WHI + (mg * 32 + mt * 16 + (lane & 15)) * 144
                              + (lane >> 4) * 16;
                #pragma unroll
                for (int ks = 0; ks < 4; ++ks) {
                    ldsm4(ahi[mt][ks], aH + ks * 32);
                    ldsm4(alo[mt][ks], aH + (WLO - WHI) + ks * 32);
                }
            }
            for (int t = 0; t < cnt; ++t) {
                int nt = nt0 + t;
                float acc[2][4] = {};
                const uint32_t bHi = arena + XHI + (nt * 8 + (lane & 7)) * 144
                                     + ((lane >> 3) & 1) * 16;
                #pragma unroll
                for (int ks = 0; ks < 4; ++ks) {
                    uint32_t bh0, bh1, bl0, bl1;
                    ldsm2(bh0, bh1, bHi + ks * 32);
                    ldsm2(bl0, bl1, bHi + (XLO - XHI) + ks * 32);
                    #pragma unroll
                    for (int mt = 0; mt < 2; ++mt) {
                        mma16816(acc[mt], ahi[mt][ks], bh0, bh1);
                        mma16816(acc[mt], ahi[mt][ks], bl0, bl1);
                        mma16816(acc[mt], alo[mt][ks], bh0, bh1);
                    }
                }
                int p = nt * 8 + 2 * (lane & 3);
                #pragma unroll
                for (int mt = 0; mt < 2; ++mt) {
                    int o = mg * 32 + mt * 16 + (lane >> 2);
                    if (p < 100) {
                        sm[OFF_HID + o * 101 + p]       = acc[mt][0];
                        sm[OFF_HID + (o + 8) * 101 + p] = acc[mt][2];
                    }
                    if (p + 1 < 100) {
                        sm[OFF_HID + o * 101 + p + 1]       = acc[mt][1];
                        sm[OFF_HID + (o + 8) * 101 + p + 1] = acc[mt][3];
                    }
                }
            }
        }
        __syncthreads();

        // depthwise 3x3: thread = (channel, 2-col group), rolling 3-row window
        {
            int ch = tid & 127, g = tid >> 7;          // g in 0..3 -> cols 2g,2g+1
            const float* wd = &sm[OFF_DW + ch * 9];
            float w0 = wd[0], w1 = wd[1], w2 = wd[2], w3 = wd[3], w4 = wd[4],
                  w5 = wd[5], w6 = wd[6], w7 = wd[7], w8 = wd[8];
            const float* hb = &sm[OFF_HID + ch * 101 + 2 * g];
            float A0r[4], B0r[4], C0r[4];
            #pragma unroll
            for (int t = 0; t < 4; ++t) { A0r[t] = hb[t]; B0r[t] = hb[10 + t]; }
            float* qrow = &sm[OFF_QKV + (c * 128 + ch) * 65 + 2 * g];
            #pragma unroll
            for (int r = 2; r < 10; ++r) {
                #pragma unroll
                for (int t = 0; t < 4; ++t) C0r[t] = hb[r * 10 + t];
                int yy = r - 2;
                #pragma unroll
                for (int e = 0; e < 2; ++e) {
                    float s = w0 * A0r[e];
                    s = fmaf(w1, A0r[e + 1], s); s = fmaf(w2, A0r[e + 2], s);
                    s = fmaf(w3, B0r[e], s);     s = fmaf(w4, B0r[e + 1], s);
                    s = fmaf(w5, B0r[e + 2], s); s = fmaf(w6, C0r[e], s);
                    s = fmaf(w7, C0r[e + 1], s); s = fmaf(w8, C0r[e + 2], s);
                    qrow[yy * 8 + e] = s;
                }
                #pragma unroll
                for (int t = 0; t < 4; ++t) { A0r[t] = B0r[t]; B0r[t] = C0r[t]; }
            }
        }
        __syncthreads();
    }

    // ---- phase 2: RMS factors for q and k (warp -> 4 pixels) ----
    #pragma unroll
    for (int pi = 0; pi < 4; ++pi) {
        int pix = warp * 4 + pi;
        float sq = 0.f, sk = 0.f;
        #pragma unroll
        for (int r = 0; r < 4; ++r) {
            int cc = lane + r * 32;
            float qv = sm[OFF_QKV + cc * 65 + pix];
            float kv = sm[OFF_QKV + (128 + cc) * 65 + pix];
            sq = fmaf(qv, qv, sq);
            sk = fmaf(kv, kv, sk);
        }
        #pragma unroll
        for (int off = 16; off; off >>= 1) {
            sq += __shfl_xor_sync(0xffffffffu, sq, off);
            sk += __shfl_xor_sync(0xffffffffu, sk, off);
        }
        if (lane == 0) {
            sm[OFF_RQ + pix] = rsqrtf(sq * (1.f / 128.f) + EPSF);
            sm[OFF_RK + pix] = rsqrtf(sk * (1.f / 128.f) + EPSF);
        }
    }
    __syncthreads();

    // ---- phase 3: RMSNorm scale + 2D RoPE (table-driven, g from smem) ----
    for (int idx = tid; idx < 64 * 64; idx += 512) {
        int m = idx >> 6, pix = idx & 63;
        int flag = (m >> 5), mm = m & 31;
        int d = flag ? (pix & 7) : (pix >> 3);
        float cs = sm[OFF_SC + flag * 256 + mm * 8 + d];
        float sn = sm[OFF_SC + 512 + flag * 256 + mm * 8 + d];
        int c0 = 2 * m;
        float rqp = sm[OFF_RQ + pix], rkp = sm[OFF_RK + pix];
        float gq0 = sm[OFF_G + 128 + c0], gq1 = sm[OFF_G + 129 + c0];
        float gk0 = sm[OFF_G + 256 + c0], gk1 = sm[OFF_G + 257 + c0];

        float q0 = sm[OFF_QKV + c0 * 65 + pix]       * rqp * gq0;
        float q1 = sm[OFF_QKV + (c0 + 1) * 65 + pix] * rqp * gq1;
        sm[OFF_QKV + c0 * 65 + pix]       = q0 * cs - q1 * sn;
        sm[OFF_QKV + (c0 + 1) * 65 + pix] = q1 * cs + q0 * sn;

        float k0 = sm[OFF_QKV + (128 + c0) * 65 + pix] * rkp * gk0;
        float k1 = sm[OFF_QKV + (129 + c0) * 65 + pix] * rkp * gk1;
        sm[OFF_QKV + (128 + c0) * 65 + pix] = k0 * cs - k1 * sn;
        sm[OFF_QKV + (129 + c0) * 65 + pix] = k1 * cs + k0 * sn;
    }

    // ---- phase 3.5: w_proj -> bf16 hi/lo tiles [o(64)][k(128)] stride 272 ----
    #pragma unroll
    for (int t = 0; t < 8; ++t) {
        int idx = tid + t * 512;
        int o = idx >> 6, kp = idx & 63;
        float2 wv = __ldg((const float2*)w_proj + idx);
        uint32_t lp, hp = pack_hi_lo(wv.x, wv.y, lp);
        *(uint32_t*)(smc + ARENA_F * 4 + WPH + o * 272 + kp * 4) = hp;
        *(uint32_t*)(smc + ARENA_F * 4 + WPL + o * 272 + kp * 4) = lp;
    }
    __syncthreads();

    // ---- phase 4: 8x8 circular conv, thread = (channel, 4 output rows) ----
    if (tid < 256) {
        int cc = tid & 127;
        int A0 = (tid >> 7) * 4;          // 0 or 4
        const float* qb = &sm[OFF_QKV + cc * 65];
        const float* kb = &sm[OFF_QKV + (128 + cc) * 65];
        float kreg[64];
        #pragma unroll
        for (int rho = 0; rho < 8; ++rho) {
            int srcRow = (rho + A0) & 7;
            #pragma unroll
            for (int col = 0; col < 8; ++col)
                kreg[rho * 8 + col] = kb[srcRow * 8 + col];
        }
        float acc[4][8] = {};
        #pragma unroll
        for (int i = 0; i < 8; ++i) {
            float qv[8];
            #pragma unroll
            for (int j = 0; j < 8; ++j) qv[j] = qb[i * 8 + j];
            #pragma unroll
            for (int j = 0; j < 8; ++j)
                #pragma unroll
                for (int a2 = 0; a2 < 4; ++a2)
                    #pragma unroll
                    for (int bb = 0; bb < 8; ++bb)
                        acc[a2][bb] = fmaf(qv[j],
                                           kreg[((a2 - i) & 7) * 8 + ((bb - j) & 7)],
                                           acc[a2][bb]);
        }
        #pragma unroll
        for (int a2 = 0; a2 < 4; ++a2)
            #pragma unroll
            for (int bb = 0; bb < 8; ++bb)
                sm[OFF_CORR + cc * 65 + (A0 + a2) * 8 + bb] = acc[a2][bb];
    }
    __syncthreads();

    // ---- phase 5: corr RMS factor (warp -> 4 pixels) ----
    #pragma unroll
    for (int pi = 0; pi < 4; ++pi) {
        int pix = warp * 4 + pi;
        float sc = 0.f;
        #pragma unroll
        for (int r = 0; r < 4; ++r) {
            float cv = sm[OFF_CORR + (lane + r * 32) * 65 + pix];
            sc = fmaf(cv, cv, sc);
        }
        #pragma unroll
        for (int off = 16; off; off >>= 1)
            sc += __shfl_xor_sync(0xffffffffu, sc, off);
        if (lane == 0)
            sm[OFF_RN + pix] = rsqrtf(sc * (1.f / 128.f) + EPSF);
    }
    __syncthreads();

    // ---- phase 6: (v * g_norm * rn * corr) -> bf16 hi/lo B tiles [pix][k] ----
    for (int idx = tid; idx < 64 * 64; idx += 512) {
        int pix = idx >> 6, kp = idx & 63;
        int k0 = 2 * kp;
        float rnp = sm[OFF_RN + pix];
        float c0v = sm[OFF_CORR + k0 * 65 + pix];
        float c1v = sm[OFF_CORR + (k0 + 1) * 65 + pix];
        float v0  = sm[OFF_QKV + (256 + k0) * 65 + pix];
        float v1  = sm[OFF_QKV + (257 + k0) * 65 + pix];
        float w0 = v0 * c0v * rnp * sm[OFF_G + k0];
        float w1 = v1 * c1v * rnp * sm[OFF_G + k0 + 1];
        uint32_t lp, hp = pack_hi_lo(w0, w1, lp);
        *(uint32_t*)(smc + ARENA_F * 4 + CBH + pix * 272 + kp * 4) = hp;
        *(uint32_t*)(smc + ARENA_F * 4 + CBL + pix * 272 + kp * 4) = lp;
    }
    __syncthreads();

    // ---- phase 7: projection HMMA, 8 warps (4m x 2n), A cached across nt ----
    if (warp < 8) {
        const int mg = warp & 3, nh = warp >> 2;
        uint32_t ahw[8][4], alw[8][4];
        const uint32_t aH = arena + WPH + (mg * 16 + (lane & 15)) * 272
                            + (lane >> 4) * 16;
        #pragma unroll
        for (int ks = 0; ks < 8; ++ks) {
            ldsm4(ahw[ks], aH + ks * 32);
            ldsm4(alw[ks], aH + (WPL - WPH) + ks * 32);
        }
        float* ob = out + (size_t)b * 64 * HH * WW;
        #pragma unroll
        for (int t = 0; t < 4; ++t) {
            int nt = nh * 4 + t;
            float acc[4] = {};
            const uint32_t bA = arena + CBH + (nt * 8 + (lane & 7)) * 272
                                + ((lane >> 3) & 1) * 16;
            #pragma unroll
            for (int ks = 0; ks < 8; ++ks) {
                uint32_t bh0, bh1, bl0, bl1;
                ldsm2(bh0, bh1, bA + ks * 32);
                ldsm2(bl0, bl1, bA + (CBL - CBH) + ks * 32);
                mma16816(acc, ahw[ks], bh0, bh1);
                mma16816(acc, ahw[ks], bl0, bl1);
                mma16816(acc, alw[ks], bh0, bh1);
            }
            int o = mg * 16 + (lane >> 2);
            int gy = gy0 + nt;
            int gxp = gx0 + 2 * (lane & 3);
            *(float2*)(ob + (size_t)o * (HH * WW) + gy * WW + gxp)
                = make_float2(acc[0], acc[1]);
            *(float2*)(ob + (size_t)(o + 8) * (HH * WW) + gy * WW + gxp)
                = make_float2(acc[2], acc[3]);
        }
    }
}

extern "C" void kernel_launch(void* const* d_in, const int* in_sizes, int n_in,
                              void* d_out, int out_size)
{
    (void)in_sizes; (void)n_in; (void)out_size;
    const float* x        = (const float*)d_in[0];
    const float* w_hidden = (const float*)d_in[1];
    const float* w_dw     = (const float*)d_in[2];
    const float* w_proj   = (const float*)d_in[3];
    const float* g_norm   = (const float*)d_in[4];
    const float* g_qnorm  = (const float*)d_in[5];
    const float* g_knorm  = (const float*)d_in[6];
    float* out = (float*)d_out;

    cudaFuncSetAttribute(fsas_fused_kernel,
                         cudaFuncAttributeMaxDynamicSharedMemorySize, SMEM_BYTES);

    dim3 grid(WW / 8, HH / 8, 4);
    fsas_fused_kernel<<<grid, 512, SMEM_BYTES>>>(
        x, w_hidden, w_dw, w_proj, g_norm, g_qnorm, g_knorm, out);
}

// round 9
// speedup vs baseline: 1.0999x; 1.0626x over previous
// FSAS_V5 fused forward — one CTA per 8x8 patch, 512 threads.
// R9: packed fma.rn.f32x2 for circ conv (parity-split) + dw conv; chunk prefetch.
#include <cuda_runtime.h>
#include <cuda_bf16.h>
#include <cstdint>

#define HH 256
#define WW 256
#define EPSF 1e-6f
#define L2T_OVER_32 0.41524101186092030f

// ---- dynamic smem layout (float offsets) ----
#define OFF_QKV  0                 // 384 * 65 fp32
#define OFF_HID  24960             // 128 * 101 fp32 hidden chunk
#define OFF_CORR OFF_HID           // 128 * 65 overlay (phase 4+)
#define OFF_G    37888             // g_norm[128], g_qnorm[128], g_knorm[128]
#define OFF_SC   38272             // sincos: cos[512], sin[512]
#define OFF_DW   39296             // 128*9 dw weights (per chunk)
#define OFF_RQ   40448
#define OFF_RK   40512
#define OFF_RN   40576
#define ARENA_F  40640             // bf16 tile arena @ byte 162,560
// phase-1 arena (rows strided 144 B -> ldmatrix conflict-free)
#define XHI 0
#define XLO 14976
#define WHI 29952
#define WLO 48384
// proj arena (rows strided 272 B); CBH..CBL+ also reused as circ-conv scratch
#define WPH 0
#define WPL 17408
#define CBH 34816
#define CBL 52224
#define ARENA_BYTES 69632
#define SMEM_BYTES (ARENA_F * 4 + ARENA_BYTES)   // 232,192 B

__device__ __forceinline__ uint32_t smem_u32(const void* p) {
    uint32_t a;
    asm("{ .reg .u64 t; cvta.to.shared.u64 t, %1; cvt.u32.u64 %0, t; }"
        : "=r"(a) : "l"(p));
    return a;
}
__device__ __forceinline__ void ldsm4(uint32_t* r, uint32_t addr) {
    asm volatile("ldmatrix.sync.aligned.m8n8.x4.shared.b16 {%0,%1,%2,%3}, [%4];"
                 : "=r"(r[0]), "=r"(r[1]), "=r"(r[2]), "=r"(r[3]) : "r"(addr));
}
__device__ __forceinline__ void ldsm2(uint32_t& r0, uint32_t& r1, uint32_t addr) {
    asm volatile("ldmatrix.sync.aligned.m8n8.x2.shared.b16 {%0,%1}, [%2];"
                 : "=r"(r0), "=r"(r1) : "r"(addr));
}
__device__ __forceinline__ void mma16816(float* c, const uint32_t* a,
                                         uint32_t b0, uint32_t b1) {
    asm volatile("mma.sync.aligned.m16n8k16.row.col.f32.bf16.bf16.f32 "
                 "{%0,%1,%2,%3}, {%4,%5,%6,%7}, {%8,%9}, {%0,%1,%2,%3};"
                 : "+f"(c[0]), "+f"(c[1]), "+f"(c[2]), "+f"(c[3])
                 : "r"(a[0]), "r"(a[1]), "r"(a[2]), "r"(a[3]), "r"(b0), "r"(b1));
}
__device__ __forceinline__ uint32_t pack_hi_lo(float v0, float v1, uint32_t& lo) {
    __nv_bfloat16 h0 = __float2bfloat16(v0);
    __nv_bfloat16 h1 = __float2bfloat16(v1);
    __nv_bfloat16 l0 = __float2bfloat16(v0 - __bfloat162float(h0));
    __nv_bfloat16 l1 = __float2bfloat16(v1 - __bfloat162float(h1));
    lo = ((uint32_t)__bfloat16_as_ushort(l1) << 16) | __bfloat16_as_ushort(l0);
    return ((uint32_t)__bfloat16_as_ushort(h1) << 16) | __bfloat16_as_ushort(h0);
}
// ---- packed f32x2 helpers ----
__device__ __forceinline__ uint64_t pk2(float lo, float hi) {
    uint64_t r; asm("mov.b64 %0, {%1, %2};" : "=l"(r) : "f"(lo), "f"(hi)); return r;
}
__device__ __forceinline__ void upk2(float& lo, float& hi, uint64_t v) {
    asm("mov.b64 {%0, %1}, %2;" : "=f"(lo), "=f"(hi) : "l"(v));
}
__device__ __forceinline__ void fma2(uint64_t& d, uint64_t a, uint64_t b) {
    asm("fma.rn.f32x2 %0, %1, %2, %0;" : "+l"(d) : "l"(a), "l"(b));
}

// circ conv body, i-parity P compile-time. Thread covers rows A0..A0+3,
// taps i in {P, P+2, P+4, P+6}. k row-pairs of single parity = no duplication.
template<int P>
__device__ __forceinline__ void circ_par(const float* qb, const float* kb,
                                         int A0, float* outv)
{
    uint64_t krp[4][8];
    #pragma unroll
    for (int t = 0; t < 4; ++t) {
        #pragma unroll
        for (int c = 0; c < 8; ++c) {
            int r0 = (2*t + P + A0) & 7;
            int r1 = (2*t + P + 1 + A0) & 7;
            krp[t][c] = pk2(kb[r0*8 + c], kb[r1*8 + c]);
        }
    }
    uint64_t acc2[2][8];
    #pragma unroll
    for (int rp = 0; rp < 2; ++rp)
        #pragma unroll
        for (int bb = 0; bb < 8; ++bb) acc2[rp][bb] = pk2(0.f, 0.f);
    #pragma unroll
    for (int ii = 0; ii < 4; ++ii) {
        const int i = P + 2*ii;
        #pragma unroll
        for (int j = 0; j < 8; ++j) {
            float qs = qb[i*8 + j];
            uint64_t qq = pk2(qs, qs);
            #pragma unroll
            for (int rp = 0; rp < 2; ++rp) {
                const int t = (rp - P - ii) & 3;
                #pragma unroll
                for (int bb = 0; bb < 8; ++bb)
                    fma2(acc2[rp][bb], qq, krp[t][(bb - j) & 7]);
            }
        }
    }
    #pragma unroll
    for (int rp = 0; rp < 2; ++rp)
        #pragma unroll
        for (int bb = 0; bb < 8; ++bb)
            upk2(outv[(2*rp)*8 + bb], outv[(2*rp+1)*8 + bb], acc2[rp][bb]);
}

__global__ __launch_bounds__(512, 1)
void fsas_fused_kernel(const float* __restrict__ x,
                       const float* __restrict__ w_hidden,
                       const float* __restrict__ w_dw,
                       const float* __restrict__ w_proj,
                       const float* __restrict__ g_norm,
                       const float* __restrict__ g_qnorm,
                       const float* __restrict__ g_knorm,
                       float* __restrict__ out)
{
    extern __shared__ float sm[];
    const int tid  = threadIdx.x;
    const int lane = tid & 31;
    const int warp = tid >> 5;
    const int px = blockIdx.x, py = blockIdx.y, b = blockIdx.z;
    const int gx0 = px * 8, gy0 = py * 8;

    char* smc = (char*)sm;
    const uint32_t sbase = smem_u32(sm);
    const uint32_t arena = sbase + ARENA_F * 4;

    // ---- prefetch chunk 0 W + dw into regs ----
    float2 wpre[8];
    float dwpre[3];
    #pragma unroll
    for (int t = 0; t < 8; ++t)
        wpre[t] = __ldg((const float2*)w_hidden + (tid + t * 512));
    #pragma unroll
    for (int t = 0; t < 3; ++t) {
        int idx = tid + t * 512;
        dwpre[t] = (idx < 1152) ? __ldg(w_dw + idx) : 0.f;
    }

    // ---- phase 0: x halo -> bf16 hi/lo Xt tiles; sincos table; g tables ----
    const float* xb = x + (size_t)b * 64 * HH * WW;
    for (int idx = tid; idx < 104 * 32; idx += 512) {
        int pos = idx >> 5, cp = idx & 31;
        float x0 = 0.f, x1 = 0.f;
        if (pos < 100) {
            int Y = pos / 10, X = pos - Y * 10;
            int gy = gy0 - 1 + Y, gx = gx0 - 1 + X;
            if ((unsigned)gy < HH && (unsigned)gx < WW) {
                size_t base = (size_t)(2 * cp) * (HH * WW) + gy * WW + gx;
                x0 = __ldg(xb + base);
                x1 = __ldg(xb + base + (size_t)(HH * WW));
            }
        }
        uint32_t lp, hp = pack_hi_lo(x0, x1, lp);
        uint32_t off = (uint32_t)(pos * 144 + cp * 4);
        *(uint32_t*)(smc + ARENA_F * 4 + XHI + off) = hp;
        *(uint32_t*)(smc + ARENA_F * 4 + XLO + off) = lp;
    }
    {   // sincos table
        int flag = tid >> 8, mm = (tid >> 3) & 31, d = tid & 7;
        float pos = (float)((flag ? gx0 : gy0) + d);
        float inv = exp2f(-L2T_OVER_32 * (float)mm);
        float sn, cs;
        sincosf(pos * inv, &sn, &cs);
        sm[OFF_SC + flag * 256 + mm * 8 + d]       = cs;
        sm[OFF_SC + 512 + flag * 256 + mm * 8 + d] = sn;
    }
    if (tid < 384) {
        float v = (tid < 128) ? __ldg(g_norm + tid)
                : (tid < 256) ? __ldg(g_qnorm + tid - 128)
                              : __ldg(g_knorm + tid - 256);
        sm[OFF_G + tid] = v;
    }
    __syncthreads();

    // ============ phase 1: expand (HMMA 4m x 4n) + depthwise, 3 chunks ============
    for (int c = 0; c < 3; ++c) {
        // STS prefetched W chunk (convert to bf16 hi/lo) + dw weights
        #pragma unroll
        for (int t = 0; t < 8; ++t) {
            int idx = tid + t * 512;
            int r = idx >> 5, cp = idx & 31;
            uint32_t lp, hp = pack_hi_lo(wpre[t].x, wpre[t].y, lp);
            uint32_t off = (uint32_t)(r * 144 + cp * 4);
            *(uint32_t*)(smc + ARENA_F * 4 + WHI + off) = hp;
            *(uint32_t*)(smc + ARENA_F * 4 + WLO + off) = lp;
        }
        #pragma unroll
        for (int t = 0; t < 3; ++t) {
            int idx = tid + t * 512;
            if (idx < 1152) sm[OFF_DW + idx] = dwpre[t];
        }
        __syncthreads();

        // prefetch next chunk (hidden under HMMA + dw)
        if (c < 2) {
            #pragma unroll
            for (int t = 0; t < 8; ++t)
                wpre[t] = __ldg((const float2*)w_hidden
                                + ((c + 1) * 4096 + tid + t * 512));
            #pragma unroll
            for (int t = 0; t < 3; ++t) {
                int idx = tid + t * 512;
                dwpre[t] = (idx < 1152) ? __ldg(w_dw + (c + 1) * 1152 + idx) : 0.f;
            }
        }

        // HMMA: warp = (mg: 32 o-rows) x (ng: nt range). A-frags cached in regs.
        {
            const int mg = warp & 3, ng = warp >> 2;
            const int nt0 = (ng == 0) ? 0 : 3 * ng + 1;
            const int cnt = (ng == 0) ? 4 : 3;
            uint32_t ahi[2][4][4], alo[2][4][4];
            #pragma unroll
            for (int mt = 0; mt < 2; ++mt) {
                uint32_t aH = arena + WHI + (mg * 32 + mt * 16 + (lane & 15)) * 144
                              + (lane >> 4) * 16;
                #pragma unroll
                for (int ks = 0; ks < 4; ++ks) {
                    ldsm4(ahi[mt][ks], aH + ks * 32);
                    ldsm4(alo[mt][ks], aH + (WLO - WHI) + ks * 32);
                }
            }
            for (int t = 0; t < cnt; ++t) {
                int nt = nt0 + t;
                float acc[2][4] = {};
                const uint32_t bHi = arena + XHI + (nt * 8 + (lane & 7)) * 144
                                     + ((lane >> 3) & 1) * 16;
                #pragma unroll
                for (int ks = 0; ks < 4; ++ks) {
                    uint32_t bh0, bh1, bl0, bl1;
                    ldsm2(bh0, bh1, bHi + ks * 32);
                    ldsm2(bl0, bl1, bHi + (XLO - XHI) + ks * 32);
                    #pragma unroll
                    for (int mt = 0; mt < 2; ++mt) {
                        mma16816(acc[mt], ahi[mt][ks], bh0, bh1);
                        mma16816(acc[mt], ahi[mt][ks], bl0, bl1);
                        mma16816(acc[mt], alo[mt][ks], bh0, bh1);
                    }
                }
                int p = nt * 8 + 2 * (lane & 3);
                #pragma unroll
                for (int mt = 0; mt < 2; ++mt) {
                    int o = mg * 32 + mt * 16 + (lane >> 2);
                    if (p < 100) {
                        sm[OFF_HID + o * 101 + p]       = acc[mt][0];
                        sm[OFF_HID + (o + 8) * 101 + p] = acc[mt][2];
                    }
                    if (p + 1 < 100) {
                        sm[OFF_HID + o * 101 + p + 1]       = acc[mt][1];
                        sm[OFF_HID + (o + 8) * 101 + p + 1] = acc[mt][3];
                    }
                }
            }
        }
        __syncthreads();

        // depthwise 3x3 (f32x2): thread = (channel, 2-col group), rolling rows
        {
            int ch = tid & 127, g = tid >> 7;
            const float* wd = &sm[OFF_DW + ch * 9];
            uint64_t ww[9];
            #pragma unroll
            for (int t = 0; t < 9; ++t) { float w = wd[t]; ww[t] = pk2(w, w); }
            const float* hb = &sm[OFF_HID + ch * 101 + 2 * g];
            uint64_t Ap[3], Bp[3], Cp[3];
            {
                float a0 = hb[0], a1 = hb[1], a2 = hb[2], a3 = hb[3];
                Ap[0] = pk2(a0, a1); Ap[1] = pk2(a1, a2); Ap[2] = pk2(a2, a3);
                float b0 = hb[10], b1 = hb[11], b2 = hb[12], b3 = hb[13];
                Bp[0] = pk2(b0, b1); Bp[1] = pk2(b1, b2); Bp[2] = pk2(b2, b3);
            }
            float* qrow = &sm[OFF_QKV + (c * 128 + ch) * 65 + 2 * g];
            #pragma unroll
            for (int r = 2; r < 10; ++r) {
                float c0 = hb[r*10+0], c1 = hb[r*10+1], c2 = hb[r*10+2], c3 = hb[r*10+3];
                Cp[0] = pk2(c0, c1); Cp[1] = pk2(c1, c2); Cp[2] = pk2(c2, c3);
                uint64_t s2 = pk2(0.f, 0.f);
                fma2(s2, ww[0], Ap[0]); fma2(s2, ww[1], Ap[1]); fma2(s2, ww[2], Ap[2]);
                fma2(s2, ww[3], Bp[0]); fma2(s2, ww[4], Bp[1]); fma2(s2, ww[5], Bp[2]);
                fma2(s2, ww[6], Cp[0]); fma2(s2, ww[7], Cp[1]); fma2(s2, ww[8], Cp[2]);
                float o0, o1; upk2(o0, o1, s2);
                int yy = r - 2;
                qrow[yy * 8 + 0] = o0; qrow[yy * 8 + 1] = o1;
                Ap[0]=Bp[0]; Ap[1]=Bp[1]; Ap[2]=Bp[2];
                Bp[0]=Cp[0]; Bp[1]=Cp[1]; Bp[2]=Cp[2];
            }
        }
        __syncthreads();
    }

    // ---- phase 1.5: prefetch w_proj into regs ----
    float2 wpj[8];
    #pragma unroll
    for (int t = 0; t < 8; ++t)
        wpj[t] = __ldg((const float2*)w_proj + (tid + t * 512));

    // ---- phase 2: RMS factors for q and k (warp -> 4 pixels) ----
    #pragma unroll
    for (int pi = 0; pi < 4; ++pi) {
        int pix = warp * 4 + pi;
        float sq = 0.f, sk = 0.f;
        #pragma unroll
        for (int r = 0; r < 4; ++r) {
            int cc = lane + r * 32;
            float qv = sm[OFF_QKV + cc * 65 + pix];
            float kv = sm[OFF_QKV + (128 + cc) * 65 + pix];
            sq = fmaf(qv, qv, sq);
            sk = fmaf(kv, kv, sk);
        }
        #pragma unroll
        for (int off = 16; off; off >>= 1) {
            sq += __shfl_xor_sync(0xffffffffu, sq, off);
            sk += __shfl_xor_sync(0xffffffffu, sk, off);
        }
        if (lane == 0) {
            sm[OFF_RQ + pix] = rsqrtf(sq * (1.f / 128.f) + EPSF);
            sm[OFF_RK + pix] = rsqrtf(sk * (1.f / 128.f) + EPSF);
        }
    }
    __syncthreads();

    // ---- phase 3: RMSNorm scale + 2D RoPE (table-driven) ----
    for (int idx = tid; idx < 64 * 64; idx += 512) {
        int m = idx >> 6, pix = idx & 63;
        int flag = (m >> 5), mm = m & 31;
        int d = flag ? (pix & 7) : (pix >> 3);
        float cs = sm[OFF_SC + flag * 256 + mm * 8 + d];
        float sn = sm[OFF_SC + 512 + flag * 256 + mm * 8 + d];
        int c0 = 2 * m;
        float rqp = sm[OFF_RQ + pix], rkp = sm[OFF_RK + pix];
        float gq0 = sm[OFF_G + 128 + c0], gq1 = sm[OFF_G + 129 + c0];
        float gk0 = sm[OFF_G + 256 + c0], gk1 = sm[OFF_G + 257 + c0];

        float q0 = sm[OFF_QKV + c0 * 65 + pix]       * rqp * gq0;
        float q1 = sm[OFF_QKV + (c0 + 1) * 65 + pix] * rqp * gq1;
        sm[OFF_QKV + c0 * 65 + pix]       = q0 * cs - q1 * sn;
        sm[OFF_QKV + (c0 + 1) * 65 + pix] = q1 * cs + q0 * sn;

        float k0 = sm[OFF_QKV + (128 + c0) * 65 + pix] * rkp * gk0;
        float k1 = sm[OFF_QKV + (129 + c0) * 65 + pix] * rkp * gk1;
        sm[OFF_QKV + (128 + c0) * 65 + pix] = k0 * cs - k1 * sn;
        sm[OFF_QKV + (129 + c0) * 65 + pix] = k1 * cs + k0 * sn;
    }

    // ---- phase 3.5: w_proj -> bf16 hi/lo tiles [o(64)][k(128)] stride 272 ----
    #pragma unroll
    for (int t = 0; t < 8; ++t) {
        int idx = tid + t * 512;
        int o = idx >> 6, kp = idx & 63;
        uint32_t lp, hp = pack_hi_lo(wpj[t].x, wpj[t].y, lp);
        *(uint32_t*)(smc + ARENA_F * 4 + WPH + o * 272 + kp * 4) = hp;
        *(uint32_t*)(smc + ARENA_F * 4 + WPL + o * 272 + kp * 4) = lp;
    }
    __syncthreads();

    // ---- phase 4: circ conv, f32x2 parity-split ----
    // thread = (ch = tid&127, rowgroup rg = (tid>>7)&1 -> A0 = 4*rg, parity P = tid>>8)
    {
        const int cc = tid & 127;
        const int A0 = ((tid >> 7) & 1) * 4;
        const int P  = tid >> 8;              // uniform per warp
        const float* qb = &sm[OFF_QKV + cc * 65];
        const float* kb = &sm[OFF_QKV + (128 + cc) * 65];
        float v32[32];
        if (P == 0) circ_par<0>(qb, kb, A0, v32);
        else        circ_par<1>(qb, kb, A0, v32);

        float* scratch = (float*)(smc + ARENA_F * 4 + CBH);   // 256 x 33 floats
        int s = tid & 255;
        if (P == 1) {
            #pragma unroll
            for (int t = 0; t < 32; ++t) scratch[s * 33 + t] = v32[t];
        }
        __syncthreads();
        if (P == 0) {
            #pragma unroll
            for (int t = 0; t < 32; ++t) {
                float tot = v32[t] + scratch[s * 33 + t];
                sm[OFF_CORR + cc * 65 + (A0 + (t >> 3)) * 8 + (t & 7)] = tot;
            }
        }
    }
    __syncthreads();

    // ---- phase 5: corr RMS factor (warp -> 4 pixels) ----
    #pragma unroll
    for (int pi = 0; pi < 4; ++pi) {
        int pix = warp * 4 + pi;
        float sc = 0.f;
        #pragma unroll
        for (int r = 0; r < 4; ++r) {
            float cv = sm[OFF_CORR + (lane + r * 32) * 65 + pix];
            sc = fmaf(cv, cv, sc);
        }
        #pragma unroll
        for (int off = 16; off; off >>= 1)
            sc += __shfl_xor_sync(0xffffffffu, sc, off);
        if (lane == 0)
            sm[OFF_RN + pix] = rsqrtf(sc * (1.f / 128.f) + EPSF);
    }
    __syncthreads();

    // ---- phase 6: (v * g_norm * rn * corr) -> bf16 hi/lo B tiles [pix][k] ----
    for (int idx = tid; idx < 64 * 64; idx += 512) {
        int pix = idx >> 6, kp = idx & 63;
        int k0 = 2 * kp;
        float rnp = sm[OFF_RN + pix];
        float c0v = sm[OFF_CORR + k0 * 65 + pix];
        float c1v = sm[OFF_CORR + (k0 + 1) * 65 + pix];
        float v0  = sm[OFF_QKV + (256 + k0) * 65 + pix];
        float v1  = sm[OFF_QKV + (257 + k0) * 65 + pix];
        float w0 = v0 * c0v * rnp * sm[OFF_G + k0];
        float w1 = v1 * c1v * rnp * sm[OFF_G + k0 + 1];
        uint32_t lp, hp = pack_hi_lo(w0, w1, lp);
        *(uint32_t*)(smc + ARENA_F * 4 + CBH + pix * 272 + kp * 4) = hp;
        *(uint32_t*)(smc + ARENA_F * 4 + CBL + pix * 272 + kp * 4) = lp;
    }
    __syncthreads();

    // ---- phase 7: projection HMMA, 8 warps (4m x 2n), A cached across nt ----
    if (warp < 8) {
        const int mg = warp & 3, nh = warp >> 2;
        uint32_t ahw[8][4], alw[8][4];
        const uint32_t aH = arena + WPH + (mg * 16 + (lane & 15)) * 272
                            + (lane >> 4) * 16;
        #pragma unroll
        for (int ks = 0; ks < 8; ++ks) {
            ldsm4(ahw[ks], aH + ks * 32);
            ldsm4(alw[ks], aH + (WPL - WPH) + ks * 32);
        }
        float* ob = out + (size_t)b * 64 * HH * WW;
        #pragma unroll
        for (int t = 0; t < 4; ++t) {
            int nt = nh * 4 + t;
            float acc[4] = {};
            const uint32_t bA = arena + CBH + (nt * 8 + (lane & 7)) * 272
                                + ((lane >> 3) & 1) * 16;
            #pragma unroll
            for (int ks = 0; ks < 8; ++ks) {
                uint32_t bh0, bh1, bl0, bl1;
                ldsm2(bh0, bh1, bA + ks * 32);
                ldsm2(bl0, bl1, bA + (CBL - CBH) + ks * 32);
                mma16816(acc, ahw[ks], bh0, bh1);
                mma16816(acc, ahw[ks], bl0, bl1);
                mma16816(acc, alw[ks], bh0, bh1);
            }
            int o = mg * 16 + (lane >> 2);
            int gy = gy0 + nt;
            int gxp = gx0 + 2 * (lane & 3);
            *(float2*)(ob + (size_t)o * (HH * WW) + gy * WW + gxp)
                = make_float2(acc[0], acc[1]);
            *(float2*)(ob + (size_t)(o + 8) * (HH * WW) + gy * WW + gxp)
                = make_float2(acc[2], acc[3]);
        }
    }
}

extern "C" void kernel_launch(void* const* d_in, const int* in_sizes, int n_in,
                              void* d_out, int out_size)
{
    (void)in_sizes; (void)n_in; (void)out_size;
    const float* x        = (const float*)d_in[0];
    const float* w_hidden = (const float*)d_in[1];
    const float* w_dw     = (const float*)d_in[2];
    const float* w_proj   = (const float*)d_in[3];
    const float* g_norm   = (const float*)d_in[4];
    const float* g_qnorm  = (const float*)d_in[5];
    const float* g_knorm  = (const float*)d_in[6];
    float* out = (float*)d_out;

    cudaFuncSetAttribute(fsas_fused_kernel,
                         cudaFuncAttributeMaxDynamicSharedMemorySize, SMEM_BYTES);

    dim3 grid(WW / 8, HH / 8, 4);
    fsas_fused_kernel<<<grid, 512, SMEM_BYTES>>>(
        x, w_hidden, w_dw, w_proj, g_norm, g_qnorm, g_knorm, out);
}

// round 11
// speedup vs baseline: 1.1280x; 1.0256x over previous
// FSAS_V5 fused forward — one CTA per 8x8 patch, 512 threads.
// R11 = R10 minus the broken barrier-diet: weights prepacked once into
// __device__ globals (arena layout, uint4 copies in main kernel);
// projection HMMA on 16 warps; R9's safe barrier/dw-buffer structure.
#include <cuda_runtime.h>
#include <cuda_bf16.h>
#include <cstdint>

#define HH 256
#define WW 256
#define EPSF 1e-6f
#define L2T_OVER_32 0.41524101186092030f

// ---- dynamic smem layout (float offsets) ----
#define OFF_QKV  0                 // 384 * 65 fp32
#define OFF_HID  24960             // 128 * 101 fp32 hidden chunk
#define OFF_CORR OFF_HID           // 128 * 65 overlay (phase 4+)
#define OFF_G    37888             // g_norm[128], g_qnorm[128], g_knorm[128]
#define OFF_SC   38272             // sincos: cos[512], sin[512]
#define OFF_DW   39296             // 128*9 dw weights (per chunk)
#define OFF_RQ   40448
#define OFF_RK   40512
#define OFF_RN   40576
#define ARENA_F  40640             // bf16 tile arena @ byte 162,560
// phase-1 arena (rows strided 144 B -> ldmatrix conflict-free)
#define XHI 0
#define XLO 14976
#define WHI 29952
#define WLO 48384
// proj arena (rows strided 272 B) — SAME bytes as phase-1 arena, reused later
#define WPH 0
#define WPL 17408
#define CBH 34816
#define CBL 52224
#define ARENA_BYTES 69632
#define SMEM_BYTES (ARENA_F * 4 + ARENA_BYTES)   // 232,192 B

// ---- prepacked weights (constant across CTAs) ----
__device__ uint32_t g_whi[3][128 * 36];   // w_hidden hi, rows 144 B
__device__ uint32_t g_wlo[3][128 * 36];   // w_hidden lo
__device__ uint32_t g_wph[64 * 68];       // w_proj hi, rows 272 B
__device__ uint32_t g_wpl[64 * 68];       // w_proj lo

__device__ __forceinline__ uint32_t smem_u32(const void* p) {
    uint32_t a;
    asm("{ .reg .u64 t; cvta.to.shared.u64 t, %1; cvt.u32.u64 %0, t; }"
        : "=r"(a) : "l"(p));
    return a;
}
__device__ __forceinline__ void ldsm4(uint32_t* r, uint32_t addr) {
    asm volatile("ldmatrix.sync.aligned.m8n8.x4.shared.b16 {%0,%1,%2,%3}, [%4];"
                 : "=r"(r[0]), "=r"(r[1]), "=r"(r[2]), "=r"(r[3]) : "r"(addr));
}
__device__ __forceinline__ void ldsm2(uint32_t& r0, uint32_t& r1, uint32_t addr) {
    asm volatile("ldmatrix.sync.aligned.m8n8.x2.shared.b16 {%0,%1}, [%2];"
                 : "=r"(r0), "=r"(r1) : "r"(addr));
}
__device__ __forceinline__ void mma16816(float* c, const uint32_t* a,
                                         uint32_t b0, uint32_t b1) {
    asm volatile("mma.sync.aligned.m16n8k16.row.col.f32.bf16.bf16.f32 "
                 "{%0,%1,%2,%3}, {%4,%5,%6,%7}, {%8,%9}, {%0,%1,%2,%3};"
                 : "+f"(c[0]), "+f"(c[1]), "+f"(c[2]), "+f"(c[3])
                 : "r"(a[0]), "r"(a[1]), "r"(a[2]), "r"(a[3]), "r"(b0), "r"(b1));
}
__device__ __forceinline__ uint32_t pack_hi_lo(float v0, float v1, uint32_t& lo) {
    __nv_bfloat16 h0 = __float2bfloat16(v0);
    __nv_bfloat16 h1 = __float2bfloat16(v1);
    __nv_bfloat16 l0 = __float2bfloat16(v0 - __bfloat162float(h0));
    __nv_bfloat16 l1 = __float2bfloat16(v1 - __bfloat162float(h1));
    lo = ((uint32_t)__bfloat16_as_ushort(l1) << 16) | __bfloat16_as_ushort(l0);
    return ((uint32_t)__bfloat16_as_ushort(h1) << 16) | __bfloat16_as_ushort(h0);
}
// ---- packed f32x2 helpers ----
__device__ __forceinline__ uint64_t pk2(float lo, float hi) {
    uint64_t r; asm("mov.b64 %0, {%1, %2};" : "=l"(r) : "f"(lo), "f"(hi)); return r;
}
__device__ __forceinline__ void upk2(float& lo, float& hi, uint64_t v) {
    asm("mov.b64 {%0, %1}, %2;" : "=f"(lo), "=f"(hi) : "l"(v));
}
__device__ __forceinline__ void fma2(uint64_t& d, uint64_t a, uint64_t b) {
    asm("fma.rn.f32x2 %0, %1, %2, %0;" : "+l"(d) : "l"(a), "l"(b));
}

// circ conv body, i-parity P compile-time (see R9).
template<int P>
__device__ __forceinline__ void circ_par(const float* qb, const float* kb,
                                         int A0, float* outv)
{
    uint64_t krp[4][8];
    #pragma unroll
    for (int t = 0; t < 4; ++t) {
        #pragma unroll
        for (int c = 0; c < 8; ++c) {
            int r0 = (2*t + P + A0) & 7;
            int r1 = (2*t + P + 1 + A0) & 7;
            krp[t][c] = pk2(kb[r0*8 + c], kb[r1*8 + c]);
        }
    }
    uint64_t acc2[2][8];
    #pragma unroll
    for (int rp = 0; rp < 2; ++rp)
        #pragma unroll
        for (int bb = 0; bb < 8; ++bb) acc2[rp][bb] = pk2(0.f, 0.f);
    #pragma unroll
    for (int ii = 0; ii < 4; ++ii) {
        const int i = P + 2*ii;
        #pragma unroll
        for (int j = 0; j < 8; ++j) {
            float qs = qb[i*8 + j];
            uint64_t qq = pk2(qs, qs);
            #pragma unroll
            for (int rp = 0; rp < 2; ++rp) {
                const int t = (rp - P - ii) & 3;
                #pragma unroll
                for (int bb = 0; bb < 8; ++bb)
                    fma2(acc2[rp][bb], qq, krp[t][(bb - j) & 7]);
            }
        }
    }
    #pragma unroll
    for (int rp = 0; rp < 2; ++rp)
        #pragma unroll
        for (int bb = 0; bb < 8; ++bb)
            upk2(outv[(2*rp)*8 + bb], outv[(2*rp+1)*8 + bb], acc2[rp][bb]);
}

// ---- prep kernel: pack constant weights into arena layout ----
__global__ void prep_weights(const float* __restrict__ w_hidden,
                             const float* __restrict__ w_proj)
{
    int t = blockIdx.x * blockDim.x + threadIdx.x;
    if (t < 3 * 128 * 32) {
        int c = t >> 12, rem = t & 4095, r = rem >> 5, cp = rem & 31;
        float2 wv = ((const float2*)w_hidden)[(c * 128 + r) * 32 + cp];
        uint32_t lp, hp = pack_hi_lo(wv.x, wv.y, lp);
        g_whi[c][r * 36 + cp] = hp;
        g_wlo[c][r * 36 + cp] = lp;
    } else if (t < 3 * 128 * 32 + 64 * 64) {
        int i = t - 3 * 128 * 32;
        int o = i >> 6, kp = i & 63;
        float2 wv = ((const float2*)w_proj)[o * 64 + kp];
        uint32_t lp, hp = pack_hi_lo(wv.x, wv.y, lp);
        g_wph[o * 68 + kp] = hp;
        g_wpl[o * 68 + kp] = lp;
    }
}

__global__ __launch_bounds__(512, 1)
void fsas_fused_kernel(const float* __restrict__ x,
                       const float* __restrict__ w_dw,
                       const float* __restrict__ g_norm,
                       const float* __restrict__ g_qnorm,
                       const float* __restrict__ g_knorm,
                       float* __restrict__ out)
{
    extern __shared__ float sm[];
    const int tid  = threadIdx.x;
    const int lane = tid & 31;
    const int warp = tid >> 5;
    const int px = blockIdx.x, py = blockIdx.y, b = blockIdx.z;
    const int gx0 = px * 8, gy0 = py * 8;

    char* smc = (char*)sm;
    const uint32_t sbase = smem_u32(sm);
    const uint32_t arena = sbase + ARENA_F * 4;

    // ---- prefetch chunk 0 W (prepacked uint4) + dw ----
    uint4 wph4[2], wpl4[2];
    float dwpre[3];
    #pragma unroll
    for (int t = 0; t < 2; ++t) {
        int w4 = tid + t * 512;
        int row = w4 >> 3, colw = (w4 & 7) * 4;
        wph4[t] = *(const uint4*)&g_whi[0][row * 36 + colw];
        wpl4[t] = *(const uint4*)&g_wlo[0][row * 36 + colw];
    }
    #pragma unroll
    for (int t = 0; t < 3; ++t) {
        int idx = tid + t * 512;
        dwpre[t] = (idx < 1152) ? __ldg(w_dw + idx) : 0.f;
    }

    // ---- phase 0: x halo -> bf16 hi/lo Xt tiles; sincos table; g tables ----
    const float* xb = x + (size_t)b * 64 * HH * WW;
    for (int idx = tid; idx < 104 * 32; idx += 512) {
        int pos = idx >> 5, cp = idx & 31;
        float x0 = 0.f, x1 = 0.f;
        if (pos < 100) {
            int Y = pos / 10, X = pos - Y * 10;
            int gy = gy0 - 1 + Y, gx = gx0 - 1 + X;
            if ((unsigned)gy < HH && (unsigned)gx < WW) {
                size_t base = (size_t)(2 * cp) * (HH * WW) + gy * WW + gx;
                x0 = __ldg(xb + base);
                x1 = __ldg(xb + base + (size_t)(HH * WW));
            }
        }
        uint32_t lp, hp = pack_hi_lo(x0, x1, lp);
        uint32_t off = (uint32_t)(pos * 144 + cp * 4);
        *(uint32_t*)(smc + ARENA_F * 4 + XHI + off) = hp;
        *(uint32_t*)(smc + ARENA_F * 4 + XLO + off) = lp;
    }
    {   // sincos table
        int flag = tid >> 8, mm = (tid >> 3) & 31, d = tid & 7;
        float pos = (float)((flag ? gx0 : gy0) + d);
        float inv = exp2f(-L2T_OVER_32 * (float)mm);
        float sn, cs;
        sincosf(pos * inv, &sn, &cs);
        sm[OFF_SC + flag * 256 + mm * 8 + d]       = cs;
        sm[OFF_SC + 512 + flag * 256 + mm * 8 + d] = sn;
    }
    if (tid < 384) {
        float v = (tid < 128) ? __ldg(g_norm + tid)
                : (tid < 256) ? __ldg(g_qnorm + tid - 128)
                              : __ldg(g_knorm + tid - 256);
        sm[OFF_G + tid] = v;
    }
    __syncthreads();

    // ============ phase 1: expand (HMMA) + depthwise, 3 chunks ============
    for (int c = 0; c < 3; ++c) {
        // STS prepacked W tiles + dw weights (single buffer at OFF_DW)
        #pragma unroll
        for (int t = 0; t < 2; ++t) {
            int w4 = tid + t * 512;
            int row = w4 >> 3, colw = (w4 & 7) * 4;
            *(uint4*)(smc + ARENA_F * 4 + WHI + row * 144 + colw * 4) = wph4[t];
            *(uint4*)(smc + ARENA_F * 4 + WLO + row * 144 + colw * 4) = wpl4[t];
        }
        #pragma unroll
        for (int t = 0; t < 3; ++t) {
            int idx = tid + t * 512;
            if (idx < 1152) sm[OFF_DW + idx] = dwpre[t];
        }
        __syncthreads();

        // prefetch next chunk (hidden under HMMA)
        if (c < 2) {
            #pragma unroll
            for (int t = 0; t < 2; ++t) {
                int w4 = tid + t * 512;
                int row = w4 >> 3, colw = (w4 & 7) * 4;
                wph4[t] = *(const uint4*)&g_whi[c + 1][row * 36 + colw];
                wpl4[t] = *(const uint4*)&g_wlo[c + 1][row * 36 + colw];
            }
            #pragma unroll
            for (int t = 0; t < 3; ++t) {
                int idx = tid + t * 512;
                dwpre[t] = (idx < 1152) ? __ldg(w_dw + (c + 1) * 1152 + idx) : 0.f;
            }
        }

        // HMMA: warp = (mg: 32 o-rows) x (ng: nt range). A-frags cached in regs.
        {
            const int mg = warp & 3, ng = warp >> 2;
            const int nt0 = (ng == 0) ? 0 : 3 * ng + 1;
            const int cnt = (ng == 0) ? 4 : 3;
            uint32_t ahi[2][4][4], alo[2][4][4];
            #pragma unroll
            for (int mt = 0; mt < 2; ++mt) {
                uint32_t aH = arena + WHI + (mg * 32 + mt * 16 + (lane & 15)) * 144
                              + (lane >> 4) * 16;
                #pragma unroll
                for (int ks = 0; ks < 4; ++ks) {
                    ldsm4(ahi[mt][ks], aH + ks * 32);
                    ldsm4(alo[mt][ks], aH + (WLO - WHI) + ks * 32);
                }
            }
            for (int t = 0; t < cnt; ++t) {
                int nt = nt0 + t;
                float acc[2][4] = {};
                const uint32_t bHi = arena + XHI + (nt * 8 + (lane & 7)) * 144
                                     + ((lane >> 3) & 1) * 16;
                #pragma unroll
                for (int ks = 0; ks < 4; ++ks) {
                    uint32_t bh0, bh1, bl0, bl1;
                    ldsm2(bh0, bh1, bHi + ks * 32);
                    ldsm2(bl0, bl1, bHi + (XLO - XHI) + ks * 32);
                    #pragma unroll
                    for (int mt = 0; mt < 2; ++mt) {
                        mma16816(acc[mt], ahi[mt][ks], bh0, bh1);
                        mma16816(acc[mt], ahi[mt][ks], bl0, bl1);
                        mma16816(acc[mt], alo[mt][ks], bh0, bh1);
                    }
                }
                int p = nt * 8 + 2 * (lane & 3);
                #pragma unroll
                for (int mt = 0; mt < 2; ++mt) {
                    int o = mg * 32 + mt * 16 + (lane >> 2);
                    if (p < 100) {
                        sm[OFF_HID + o * 101 + p]       = acc[mt][0];
                        sm[OFF_HID + (o + 8) * 101 + p] = acc[mt][2];
                    }
                    if (p + 1 < 100) {
                        sm[OFF_HID + o * 101 + p + 1]       = acc[mt][1];
                        sm[OFF_HID + (o + 8) * 101 + p + 1] = acc[mt][3];
                    }
                }
            }
        }
        __syncthreads();

        // depthwise 3x3 (f32x2), thread = (channel, 2-col group), rolling rows
        {
            int ch = tid & 127, g = tid >> 7;
            const float* wd = &sm[OFF_DW + ch * 9];
            uint64_t ww[9];
            #pragma unroll
            for (int t = 0; t < 9; ++t) { float w = wd[t]; ww[t] = pk2(w, w); }
            const float* hb = &sm[OFF_HID + ch * 101 + 2 * g];
            uint64_t Ap[3], Bp[3], Cp[3];
            {
                float a0 = hb[0], a1 = hb[1], a2 = hb[2], a3 = hb[3];
                Ap[0] = pk2(a0, a1); Ap[1] = pk2(a1, a2); Ap[2] = pk2(a2, a3);
                float b0 = hb[10], b1 = hb[11], b2 = hb[12], b3 = hb[13];
                Bp[0] = pk2(b0, b1); Bp[1] = pk2(b1, b2); Bp[2] = pk2(b2, b3);
            }
            float* qrow = &sm[OFF_QKV + (c * 128 + ch) * 65 + 2 * g];
            #pragma unroll
            for (int r = 2; r < 10; ++r) {
                float c0 = hb[r*10+0], c1 = hb[r*10+1], c2 = hb[r*10+2], c3 = hb[r*10+3];
                Cp[0] = pk2(c0, c1); Cp[1] = pk2(c1, c2); Cp[2] = pk2(c2, c3);
                uint64_t s2 = pk2(0.f, 0.f);
                fma2(s2, ww[0], Ap[0]); fma2(s2, ww[1], Ap[1]); fma2(s2, ww[2], Ap[2]);
                fma2(s2, ww[3], Bp[0]); fma2(s2, ww[4], Bp[1]); fma2(s2, ww[5], Bp[2]);
                fma2(s2, ww[6], Cp[0]); fma2(s2, ww[7], Cp[1]); fma2(s2, ww[8], Cp[2]);
                float o0, o1; upk2(o0, o1, s2);
                int yy = r - 2;
                qrow[yy * 8 + 0] = o0; qrow[yy * 8 + 1] = o1;
                Ap[0]=Bp[0]; Ap[1]=Bp[1]; Ap[2]=Bp[2];
                Bp[0]=Cp[0]; Bp[1]=Cp[1]; Bp[2]=Cp[2];
            }
        }
        __syncthreads();
    }

    // ---- prefetch w_proj (prepacked) into regs ----
    uint4 pjh[2], pjl[2];
    #pragma unroll
    for (int t = 0; t < 2; ++t) {
        int w4 = tid + t * 512;
        int row = w4 >> 4, colw = (w4 & 15) * 4;
        pjh[t] = *(const uint4*)&g_wph[row * 68 + colw];
        pjl[t] = *(const uint4*)&g_wpl[row * 68 + colw];
    }

    // ---- phase 2: RMS factors for q and k (warp -> 4 pixels) ----
    #pragma unroll
    for (int pi = 0; pi < 4; ++pi) {
        int pix = warp * 4 + pi;
        float sq = 0.f, sk = 0.f;
        #pragma unroll
        for (int r = 0; r < 4; ++r) {
            int cc = lane + r * 32;
            float qv = sm[OFF_QKV + cc * 65 + pix];
            float kv = sm[OFF_QKV + (128 + cc) * 65 + pix];
            sq = fmaf(qv, qv, sq);
            sk = fmaf(kv, kv, sk);
        }
        #pragma unroll
        for (int off = 16; off; off >>= 1) {
            sq += __shfl_xor_sync(0xffffffffu, sq, off);
            sk += __shfl_xor_sync(0xffffffffu, sk, off);
        }
        if (lane == 0) {
            sm[OFF_RQ + pix] = rsqrtf(sq * (1.f / 128.f) + EPSF);
            sm[OFF_RK + pix] = rsqrtf(sk * (1.f / 128.f) + EPSF);
        }
    }
    __syncthreads();

    // ---- phase 3: RMSNorm scale + 2D RoPE (table-driven) ----
    for (int idx = tid; idx < 64 * 64; idx += 512) {
        int m = idx >> 6, pix = idx & 63;
        int flag = (m >> 5), mm = m & 31;
        int d = flag ? (pix & 7) : (pix >> 3);
        float cs = sm[OFF_SC + flag * 256 + mm * 8 + d];
        float sn = sm[OFF_SC + 512 + flag * 256 + mm * 8 + d];
        int c0 = 2 * m;
        float rqp = sm[OFF_RQ + pix], rkp = sm[OFF_RK + pix];
        float gq0 = sm[OFF_G + 128 + c0], gq1 = sm[OFF_G + 129 + c0];
        float gk0 = sm[OFF_G + 256 + c0], gk1 = sm[OFF_G + 257 + c0];

        float q0 = sm[OFF_QKV + c0 * 65 + pix]       * rqp * gq0;
        float q1 = sm[OFF_QKV + (c0 + 1) * 65 + pix] * rqp * gq1;
        sm[OFF_QKV + c0 * 65 + pix]       = q0 * cs - q1 * sn;
        sm[OFF_QKV + (c0 + 1) * 65 + pix] = q1 * cs + q0 * sn;

        float k0 = sm[OFF_QKV + (128 + c0) * 65 + pix] * rkp * gk0;
        float k1 = sm[OFF_QKV + (129 + c0) * 65 + pix] * rkp * gk1;
        sm[OFF_QKV + (128 + c0) * 65 + pix] = k0 * cs - k1 * sn;
        sm[OFF_QKV + (129 + c0) * 65 + pix] = k1 * cs + k0 * sn;
    }

    // ---- phase 3.5: w_proj tiles via uint4 copy (phase-1 arena now dead) ----
    #pragma unroll
    for (int t = 0; t < 2; ++t) {
        int w4 = tid + t * 512;
        int row = w4 >> 4, colw = (w4 & 15) * 4;
        *(uint4*)(smc + ARENA_F * 4 + WPH + row * 272 + colw * 4) = pjh[t];
        *(uint4*)(smc + ARENA_F * 4 + WPL + row * 272 + colw * 4) = pjl[t];
    }
    __syncthreads();

    // ---- phase 4: circ conv, f32x2 parity-split ----
    {
        const int cc = tid & 127;
        const int A0 = ((tid >> 7) & 1) * 4;
        const int P  = tid >> 8;
        const float* qb = &sm[OFF_QKV + cc * 65];
        const float* kb = &sm[OFF_QKV + (128 + cc) * 65];
        float v32[32];
        if (P == 0) circ_par<0>(qb, kb, A0, v32);
        else        circ_par<1>(qb, kb, A0, v32);

        float* scratch = (float*)(smc + ARENA_F * 4 + CBH);   // 256 x 33 floats
        int s = tid & 255;
        if (P == 1) {
            #pragma unroll
            for (int t = 0; t < 32; ++t) scratch[s * 33 + t] = v32[t];
        }
        __syncthreads();
        if (P == 0) {
            #pragma unroll
            for (int t = 0; t < 32; ++t) {
                float tot = v32[t] + scratch[s * 33 + t];
                sm[OFF_CORR + cc * 65 + (A0 + (t >> 3)) * 8 + (t & 7)] = tot;
            }
        }
    }
    __syncthreads();

    // ---- phase 5: corr RMS factor (warp -> 4 pixels) ----
    #pragma unroll
    for (int pi = 0; pi < 4; ++pi) {
        int pix = warp * 4 + pi;
        float sc = 0.f;
        #pragma unroll
        for (int r = 0; r < 4; ++r) {
            float cv = sm[OFF_CORR + (lane + r * 32) * 65 + pix];
            sc = fmaf(cv, cv, sc);
        }
        #pragma unroll
        for (int off = 16; off; off >>= 1)
            sc += __shfl_xor_sync(0xffffffffu, sc, off);
        if (lane == 0)
            sm[OFF_RN + pix] = rsqrtf(sc * (1.f / 128.f) + EPSF);
    }
    __syncthreads();

    // ---- phase 6: (v * g_norm * rn * corr) -> bf16 hi/lo B tiles [pix][k] ----
    for (int idx = tid; idx < 64 * 64; idx += 512) {
        int pix = idx >> 6, kp = idx & 63;
        int k0 = 2 * kp;
        float rnp = sm[OFF_RN + pix];
        float c0v = sm[OFF_CORR + k0 * 65 + pix];
        float c1v = sm[OFF_CORR + (k0 + 1) * 65 + pix];
        float v0  = sm[OFF_QKV + (256 + k0) * 65 + pix];
        float v1  = sm[OFF_QKV + (257 + k0) * 65 + pix];
        float w0 = v0 * c0v * rnp * sm[OFF_G + k0];
        float w1 = v1 * c1v * rnp * sm[OFF_G + k0 + 1];
        uint32_t lp, hp = pack_hi_lo(w0, w1, lp);
        *(uint32_t*)(smc + ARENA_F * 4 + CBH + pix * 272 + kp * 4) = hp;
        *(uint32_t*)(smc + ARENA_F * 4 + CBL + pix * 272 + kp * 4) = lp;
    }
    __syncthreads();

    // ---- phase 7: projection HMMA on 16 warps (4 mg x 4 nh, 2 nt each) ----
    if (warp < 16) {
        const int mg = warp & 3, nh = warp >> 2;
        uint32_t ahw[8][4], alw[8][4];
        const uint32_t aH = arena + WPH + (mg * 16 + (lane & 15)) * 272
                            + (lane >> 4) * 16;
        #pragma unroll
        for (int ks = 0; ks < 8; ++ks) {
            ldsm4(ahw[ks], aH + ks * 32);
            ldsm4(alw[ks], aH + (WPL - WPH) + ks * 32);
        }
        float* ob = out + (size_t)b * 64 * HH * WW;
        #pragma unroll
        for (int t = 0; t < 2; ++t) {
            int nt = nh * 2 + t;
            float acc[4] = {};
            const uint32_t bA = arena + CBH + (nt * 8 + (lane & 7)) * 272
                                + ((lane >> 3) & 1) * 16;
            #pragma unroll
            for (int ks = 0; ks < 8; ++ks) {
                uint32_t bh0, bh1, bl0, bl1;
                ldsm2(bh0, bh1, bA + ks * 32);
                ldsm2(bl0, bl1, bA + (CBL - CBH) + ks * 32);
                mma16816(acc, ahw[ks], bh0, bh1);
                mma16816(acc, ahw[ks], bl0, bl1);
                mma16816(acc, alw[ks], bh0, bh1);
            }
            int o = mg * 16 + (lane >> 2);
            int gy = gy0 + nt;
            int gxp = gx0 + 2 * (lane & 3);
            *(float2*)(ob + (size_t)o * (HH * WW) + gy * WW + gxp)
                = make_float2(acc[0], acc[1]);
            *(float2*)(ob + (size_t)(o + 8) * (HH * WW) + gy * WW + gxp)
                = make_float2(acc[2], acc[3]);
        }
    }
}

extern "C" void kernel_launch(void* const* d_in, const int* in_sizes, int n_in,
                              void* d_out, int out_size)
{
    (void)in_sizes; (void)n_in; (void)out_size;
    const float* x        = (const float*)d_in[0];
    const float* w_hidden = (const float*)d_in[1];
    const float* w_dw     = (const float*)d_in[2];
    const float* w_proj   = (const float*)d_in[3];
    const float* g_norm   = (const float*)d_in[4];
    const float* g_qnorm  = (const float*)d_in[5];
    const float* g_knorm  = (const float*)d_in[6];
    float* out = (float*)d_out;

    prep_weights<<<64, 256>>>(w_hidden, w_proj);

    cudaFuncSetAttribute(fsas_fused_kernel,
                         cudaFuncAttributeMaxDynamicSharedMemorySize, SMEM_BYTES);
    dim3 grid(WW / 8, HH / 8, 4);
    fsas_fused_kernel<<<grid, 512, SMEM_BYTES>>>(
        x, w_dw, g_norm, g_qnorm, g_knorm, out);
}

// round 12
// speedup vs baseline: 1.1707x; 1.0378x over previous
// FSAS_V5 fused forward — one CTA per 8x8 patch, 512 threads.
// R12 = R11 + coalesced x-halo loads (lane ↦ position, not channel) and
// chunk-0 weight STS hoisted into phase 0 (one fewer barrier, overlapped).
#include <cuda_runtime.h>
#include <cuda_bf16.h>
#include <cstdint>

#define HH 256
#define WW 256
#define EPSF 1e-6f
#define L2T_OVER_32 0.41524101186092030f

// ---- dynamic smem layout (float offsets) ----
#define OFF_QKV  0                 // 384 * 65 fp32
#define OFF_HID  24960             // 128 * 101 fp32 hidden chunk
#define OFF_CORR OFF_HID           // 128 * 65 overlay (phase 4+)
#define OFF_G    37888             // g_norm[128], g_qnorm[128], g_knorm[128]
#define OFF_SC   38272             // sincos: cos[512], sin[512]
#define OFF_DW   39296             // 128*9 dw weights (per chunk)
#define OFF_RQ   40448
#define OFF_RK   40512
#define OFF_RN   40576
#define ARENA_F  40640             // bf16 tile arena @ byte 162,560
// phase-1 arena (rows strided 144 B -> ldmatrix conflict-free)
#define XHI 0
#define XLO 14976
#define WHI 29952
#define WLO 48384
// proj arena (rows strided 272 B) — SAME bytes as phase-1 arena, reused later
#define WPH 0
#define WPL 17408
#define CBH 34816
#define CBL 52224
#define ARENA_BYTES 69632
#define SMEM_BYTES (ARENA_F * 4 + ARENA_BYTES)   // 232,192 B

// ---- prepacked weights (constant across CTAs) ----
__device__ uint32_t g_whi[3][128 * 36];   // w_hidden hi, rows 144 B
__device__ uint32_t g_wlo[3][128 * 36];   // w_hidden lo
__device__ uint32_t g_wph[64 * 68];       // w_proj hi, rows 272 B
__device__ uint32_t g_wpl[64 * 68];       // w_proj lo

__device__ __forceinline__ uint32_t smem_u32(const void* p) {
    uint32_t a;
    asm("{ .reg .u64 t; cvta.to.shared.u64 t, %1; cvt.u32.u64 %0, t; }"
        : "=r"(a) : "l"(p));
    return a;
}
__device__ __forceinline__ void ldsm4(uint32_t* r, uint32_t addr) {
    asm volatile("ldmatrix.sync.aligned.m8n8.x4.shared.b16 {%0,%1,%2,%3}, [%4];"
                 : "=r"(r[0]), "=r"(r[1]), "=r"(r[2]), "=r"(r[3]) : "r"(addr));
}
__device__ __forceinline__ void ldsm2(uint32_t& r0, uint32_t& r1, uint32_t addr) {
    asm volatile("ldmatrix.sync.aligned.m8n8.x2.shared.b16 {%0,%1}, [%2];"
                 : "=r"(r0), "=r"(r1) : "r"(addr));
}
__device__ __forceinline__ void mma16816(float* c, const uint32_t* a,
                                         uint32_t b0, uint32_t b1) {
    asm volatile("mma.sync.aligned.m16n8k16.row.col.f32.bf16.bf16.f32 "
                 "{%0,%1,%2,%3}, {%4,%5,%6,%7}, {%8,%9}, {%0,%1,%2,%3};"
                 : "+f"(c[0]), "+f"(c[1]), "+f"(c[2]), "+f"(c[3])
                 : "r"(a[0]), "r"(a[1]), "r"(a[2]), "r"(a[3]), "r"(b0), "r"(b1));
}
__device__ __forceinline__ uint32_t pack_hi_lo(float v0, float v1, uint32_t& lo) {
    __nv_bfloat16 h0 = __float2bfloat16(v0);
    __nv_bfloat16 h1 = __float2bfloat16(v1);
    __nv_bfloat16 l0 = __float2bfloat16(v0 - __bfloat162float(h0));
    __nv_bfloat16 l1 = __float2bfloat16(v1 - __bfloat162float(h1));
    lo = ((uint32_t)__bfloat16_as_ushort(l1) << 16) | __bfloat16_as_ushort(l0);
    return ((uint32_t)__bfloat16_as_ushort(h1) << 16) | __bfloat16_as_ushort(h0);
}
// ---- packed f32x2 helpers ----
__device__ __forceinline__ uint64_t pk2(float lo, float hi) {
    uint64_t r; asm("mov.b64 %0, {%1, %2};" : "=l"(r) : "f"(lo), "f"(hi)); return r;
}
__device__ __forceinline__ void upk2(float& lo, float& hi, uint64_t v) {
    asm("mov.b64 {%0, %1}, %2;" : "=f"(lo), "=f"(hi) : "l"(v));
}
__device__ __forceinline__ void fma2(uint64_t& d, uint64_t a, uint64_t b) {
    asm("fma.rn.f32x2 %0, %1, %2, %0;" : "+l"(d) : "l"(a), "l"(b));
}

// circ conv body, i-parity P compile-time (see R9).
template<int P>
__device__ __forceinline__ void circ_par(const float* qb, const float* kb,
                                         int A0, float* outv)
{
    uint64_t krp[4][8];
    #pragma unroll
    for (int t = 0; t < 4; ++t) {
        #pragma unroll
        for (int c = 0; c < 8; ++c) {
            int r0 = (2*t + P + A0) & 7;
            int r1 = (2*t + P + 1 + A0) & 7;
            krp[t][c] = pk2(kb[r0*8 + c], kb[r1*8 + c]);
        }
    }
    uint64_t acc2[2][8];
    #pragma unroll
    for (int rp = 0; rp < 2; ++rp)
        #pragma unroll
        for (int bb = 0; bb < 8; ++bb) acc2[rp][bb] = pk2(0.f, 0.f);
    #pragma unroll
    for (int ii = 0; ii < 4; ++ii) {
        const int i = P + 2*ii;
        #pragma unroll
        for (int j = 0; j < 8; ++j) {
            float qs = qb[i*8 + j];
            uint64_t qq = pk2(qs, qs);
            #pragma unroll
            for (int rp = 0; rp < 2; ++rp) {
                const int t = (rp - P - ii) & 3;
                #pragma unroll
                for (int bb = 0; bb < 8; ++bb)
                    fma2(acc2[rp][bb], qq, krp[t][(bb - j) & 7]);
            }
        }
    }
    #pragma unroll
    for (int rp = 0; rp < 2; ++rp)
        #pragma unroll
        for (int bb = 0; bb < 8; ++bb)
            upk2(outv[(2*rp)*8 + bb], outv[(2*rp+1)*8 + bb], acc2[rp][bb]);
}

// ---- prep kernel: pack constant weights into arena layout ----
__global__ void prep_weights(const float* __restrict__ w_hidden,
                             const float* __restrict__ w_proj)
{
    int t = blockIdx.x * blockDim.x + threadIdx.x;
    if (t < 3 * 128 * 32) {
        int c = t >> 12, rem = t & 4095, r = rem >> 5, cp = rem & 31;
        float2 wv = ((const float2*)w_hidden)[(c * 128 + r) * 32 + cp];
        uint32_t lp, hp = pack_hi_lo(wv.x, wv.y, lp);
        g_whi[c][r * 36 + cp] = hp;
        g_wlo[c][r * 36 + cp] = lp;
    } else if (t < 3 * 128 * 32 + 64 * 64) {
        int i = t - 3 * 128 * 32;
        int o = i >> 6, kp = i & 63;
        float2 wv = ((const float2*)w_proj)[o * 64 + kp];
        uint32_t lp, hp = pack_hi_lo(wv.x, wv.y, lp);
        g_wph[o * 68 + kp] = hp;
        g_wpl[o * 68 + kp] = lp;
    }
}

__global__ __launch_bounds__(512, 1)
void fsas_fused_kernel(const float* __restrict__ x,
                       const float* __restrict__ w_dw,
                       const float* __restrict__ g_norm,
                       const float* __restrict__ g_qnorm,
                       const float* __restrict__ g_knorm,
                       float* __restrict__ out)
{
    extern __shared__ float sm[];
    const int tid  = threadIdx.x;
    const int lane = tid & 31;
    const int warp = tid >> 5;
    const int px = blockIdx.x, py = blockIdx.y, b = blockIdx.z;
    const int gx0 = px * 8, gy0 = py * 8;

    char* smc = (char*)sm;
    const uint32_t sbase = smem_u32(sm);
    const uint32_t arena = sbase + ARENA_F * 4;

    // ---- prefetch chunk 0 W (prepacked uint4) + dw ----
    uint4 wph4[2], wpl4[2];
    float dwpre[3];
    #pragma unroll
    for (int t = 0; t < 2; ++t) {
        int w4 = tid + t * 512;
        int row = w4 >> 3, colw = (w4 & 7) * 4;
        wph4[t] = *(const uint4*)&g_whi[0][row * 36 + colw];
        wpl4[t] = *(const uint4*)&g_wlo[0][row * 36 + colw];
    }
    #pragma unroll
    for (int t = 0; t < 3; ++t) {
        int idx = tid + t * 512;
        dwpre[t] = (idx < 1152) ? __ldg(w_dw + idx) : 0.f;
    }

    // ---- phase 0: x halo (COALESCED: lane = 4 ch-pairs x 8 consecutive pos) ----
    const float* xb = x + (size_t)b * 64 * HH * WW;
    for (int it = warp; it < 104; it += 16) {
        int cpBase = it / 13;
        int posBase = it - cpBase * 13;
        int cp  = cpBase * 4 + (lane >> 3);       // 0..31 channel-pair
        int pos = posBase * 8 + (lane & 7);       // 0..103
        float x0 = 0.f, x1 = 0.f;
        if (pos < 100) {
            int Y = pos / 10, X = pos - Y * 10;
            int gy = gy0 - 1 + Y, gx = gx0 - 1 + X;
            if ((unsigned)gy < HH && (unsigned)gx < WW) {
                size_t base = (size_t)(2 * cp) * (HH * WW) + gy * WW + gx;
                x0 = __ldg(xb + base);
                x1 = __ldg(xb + base + (size_t)(HH * WW));
            }
        }
        uint32_t lp, hp = pack_hi_lo(x0, x1, lp);
        uint32_t off = (uint32_t)(pos * 144 + cp * 4);
        *(uint32_t*)(smc + ARENA_F * 4 + XHI + off) = hp;
        *(uint32_t*)(smc + ARENA_F * 4 + XLO + off) = lp;
    }
    {   // sincos table
        int flag = tid >> 8, mm = (tid >> 3) & 31, d = tid & 7;
        float pos = (float)((flag ? gx0 : gy0) + d);
        float inv = exp2f(-L2T_OVER_32 * (float)mm);
        float sn, cs;
        sincosf(pos * inv, &sn, &cs);
        sm[OFF_SC + flag * 256 + mm * 8 + d]       = cs;
        sm[OFF_SC + 512 + flag * 256 + mm * 8 + d] = sn;
    }
    if (tid < 384) {
        float v = (tid < 128) ? __ldg(g_norm + tid)
                : (tid < 256) ? __ldg(g_qnorm + tid - 128)
                              : __ldg(g_knorm + tid - 256);
        sm[OFF_G + tid] = v;
    }
    // chunk-0 W/dw STS hoisted here (overlaps the halo LDG latency)
    #pragma unroll
    for (int t = 0; t < 2; ++t) {
        int w4 = tid + t * 512;
        int row = w4 >> 3, colw = (w4 & 7) * 4;
        *(uint4*)(smc + ARENA_F * 4 + WHI + row * 144 + colw * 4) = wph4[t];
        *(uint4*)(smc + ARENA_F * 4 + WLO + row * 144 + colw * 4) = wpl4[t];
    }
    #pragma unroll
    for (int t = 0; t < 3; ++t) {
        int idx = tid + t * 512;
        if (idx < 1152) sm[OFF_DW + idx] = dwpre[t];
    }
    __syncthreads();

    // ============ phase 1: expand (HMMA) + depthwise, 3 chunks ============
    for (int c = 0; c < 3; ++c) {
        if (c > 0) {
            #pragma unroll
            for (int t = 0; t < 2; ++t) {
                int w4 = tid + t * 512;
                int row = w4 >> 3, colw = (w4 & 7) * 4;
                *(uint4*)(smc + ARENA_F * 4 + WHI + row * 144 + colw * 4) = wph4[t];
                *(uint4*)(smc + ARENA_F * 4 + WLO + row * 144 + colw * 4) = wpl4[t];
            }
            #pragma unroll
            for (int t = 0; t < 3; ++t) {
                int idx = tid + t * 512;
                if (idx < 1152) sm[OFF_DW + idx] = dwpre[t];
            }
            __syncthreads();
        }
        // prefetch next chunk (hidden under HMMA)
        if (c < 2) {
            #pragma unroll
            for (int t = 0; t < 2; ++t) {
                int w4 = tid + t * 512;
                int row = w4 >> 3, colw = (w4 & 7) * 4;
                wph4[t] = *(const uint4*)&g_whi[c + 1][row * 36 + colw];
                wpl4[t] = *(const uint4*)&g_wlo[c + 1][row * 36 + colw];
            }
            #pragma unroll
            for (int t = 0; t < 3; ++t) {
                int idx = tid + t * 512;
                dwpre[t] = (idx < 1152) ? __ldg(w_dw + (c + 1) * 1152 + idx) : 0.f;
            }
        }

        // HMMA: warp = (mg: 32 o-rows) x (ng: nt range). A-frags cached in regs.
        {
            const int mg = warp & 3, ng = warp >> 2;
            const int nt0 = (ng == 0) ? 0 : 3 * ng + 1;
            const int cnt = (ng == 0) ? 4 : 3;
            uint32_t ahi[2][4][4], alo[2][4][4];
            #pragma unroll
            for (int mt = 0; mt < 2; ++mt) {
                uint32_t aH = arena + WHI + (mg * 32 + mt * 16 + (lane & 15)) * 144
                              + (lane >> 4) * 16;
                #pragma unroll
                for (int ks = 0; ks < 4; ++ks) {
                    ldsm4(ahi[mt][ks], aH + ks * 32);
                    ldsm4(alo[mt][ks], aH + (WLO - WHI) + ks * 32);
                }
            }
            for (int t = 0; t < cnt; ++t) {
                int nt = nt0 + t;
                float acc[2][4] = {};
                const uint32_t bHi = arena + XHI + (nt * 8 + (lane & 7)) * 144
                                     + ((lane >> 3) & 1) * 16;
                #pragma unroll
                for (int ks = 0; ks < 4; ++ks) {
                    uint32_t bh0, bh1, bl0, bl1;
                    ldsm2(bh0, bh1, bHi + ks * 32);
                    ldsm2(bl0, bl1, bHi + (XLO - XHI) + ks * 32);
                    #pragma unroll
                    for (int mt = 0; mt < 2; ++mt) {
                        mma16816(acc[mt], ahi[mt][ks], bh0, bh1);
                        mma16816(acc[mt], ahi[mt][ks], bl0, bl1);
                        mma16816(acc[mt], alo[mt][ks], bh0, bh1);
                    }
                }
                int p = nt * 8 + 2 * (lane & 3);
                #pragma unroll
                for (int mt = 0; mt < 2; ++mt) {
                    int o = mg * 32 + mt * 16 + (lane >> 2);
                    if (p < 100) {
                        sm[OFF_HID + o * 101 + p]       = acc[mt][0];
                        sm[OFF_HID + (o + 8) * 101 + p] = acc[mt][2];
                    }
                    if (p + 1 < 100) {
                        sm[OFF_HID + o * 101 + p + 1]       = acc[mt][1];
                        sm[OFF_HID + (o + 8) * 101 + p + 1] = acc[mt][3];
                    }
                }
            }
        }
        __syncthreads();

        // depthwise 3x3 (f32x2), thread = (channel, 2-col group), rolling rows
        {
            int ch = tid & 127, g = tid >> 7;
            const float* wd = &sm[OFF_DW + ch * 9];
            uint64_t ww[9];
            #pragma unroll
            for (int t = 0; t < 9; ++t) { float w = wd[t]; ww[t] = pk2(w, w); }
            const float* hb = &sm[OFF_HID + ch * 101 + 2 * g];
            uint64_t Ap[3], Bp[3], Cp[3];
            {
                float a0 = hb[0], a1 = hb[1], a2 = hb[2], a3 = hb[3];
                Ap[0] = pk2(a0, a1); Ap[1] = pk2(a1, a2); Ap[2] = pk2(a2, a3);
                float b0 = hb[10], b1 = hb[11], b2 = hb[12], b3 = hb[13];
                Bp[0] = pk2(b0, b1); Bp[1] = pk2(b1, b2); Bp[2] = pk2(b2, b3);
            }
            float* qrow = &sm[OFF_QKV + (c * 128 + ch) * 65 + 2 * g];
            #pragma unroll
            for (int r = 2; r < 10; ++r) {
                float c0 = hb[r*10+0], c1 = hb[r*10+1], c2 = hb[r*10+2], c3 = hb[r*10+3];
                Cp[0] = pk2(c0, c1); Cp[1] = pk2(c1, c2); Cp[2] = pk2(c2, c3);
                uint64_t s2 = pk2(0.f, 0.f);
                fma2(s2, ww[0], Ap[0]); fma2(s2, ww[1], Ap[1]); fma2(s2, ww[2], Ap[2]);
                fma2(s2, ww[3], Bp[0]); fma2(s2, ww[4], Bp[1]); fma2(s2, ww[5], Bp[2]);
                fma2(s2, ww[6], Cp[0]); fma2(s2, ww[7], Cp[1]); fma2(s2, ww[8], Cp[2]);
                float o0, o1; upk2(o0, o1, s2);
                int yy = r - 2;
                qrow[yy * 8 + 0] = o0; qrow[yy * 8 + 1] = o1;
                Ap[0]=Bp[0]; Ap[1]=Bp[1]; Ap[2]=Bp[2];
                Bp[0]=Cp[0]; Bp[1]=Cp[1]; Bp[2]=Cp[2];
            }
        }
        __syncthreads();
    }

    // ---- prefetch w_proj (prepacked) into regs ----
    uint4 pjh[2], pjl[2];
    #pragma unroll
    for (int t = 0; t < 2; ++t) {
        int w4 = tid + t * 512;
        int row = w4 >> 4, colw = (w4 & 15) * 4;
        pjh[t] = *(const uint4*)&g_wph[row * 68 + colw];
        pjl[t] = *(const uint4*)&g_wpl[row * 68 + colw];
    }

    // ---- phase 2: RMS factors for q and k (warp -> 4 pixels) ----
    #pragma unroll
    for (int pi = 0; pi < 4; ++pi) {
        int pix = warp * 4 + pi;
        float sq = 0.f, sk = 0.f;
        #pragma unroll
        for (int r = 0; r < 4; ++r) {
            int cc = lane + r * 32;
            float qv = sm[OFF_QKV + cc * 65 + pix];
            float kv = sm[OFF_QKV + (128 + cc) * 65 + pix];
            sq = fmaf(qv, qv, sq);
            sk = fmaf(kv, kv, sk);
        }
        #pragma unroll
        for (int off = 16; off; off >>= 1) {
            sq += __shfl_xor_sync(0xffffffffu, sq, off);
            sk += __shfl_xor_sync(0xffffffffu, sk, off);
        }
        if (lane == 0) {
            sm[OFF_RQ + pix] = rsqrtf(sq * (1.f / 128.f) + EPSF);
            sm[OFF_RK + pix] = rsqrtf(sk * (1.f / 128.f) + EPSF);
        }
    }
    __syncthreads();

    // ---- phase 3: RMSNorm scale + 2D RoPE (table-driven) ----
    for (int idx = tid; idx < 64 * 64; idx += 512) {
        int m = idx >> 6, pix = idx & 63;
        int flag = (m >> 5), mm = m & 31;
        int d = flag ? (pix & 7) : (pix >> 3);
        float cs = sm[OFF_SC + flag * 256 + mm * 8 + d];
        float sn = sm[OFF_SC + 512 + flag * 256 + mm * 8 + d];
        int c0 = 2 * m;
        float rqp = sm[OFF_RQ + pix], rkp = sm[OFF_RK + pix];
        float gq0 = sm[OFF_G + 128 + c0], gq1 = sm[OFF_G + 129 + c0];
        float gk0 = sm[OFF_G + 256 + c0], gk1 = sm[OFF_G + 257 + c0];

        float q0 = sm[OFF_QKV + c0 * 65 + pix]       * rqp * gq0;
        float q1 = sm[OFF_QKV + (c0 + 1) * 65 + pix] * rqp * gq1;
        sm[OFF_QKV + c0 * 65 + pix]       = q0 * cs - q1 * sn;
        sm[OFF_QKV + (c0 + 1) * 65 + pix] = q1 * cs + q0 * sn;

        float k0 = sm[OFF_QKV + (128 + c0) * 65 + pix] * rkp * gk0;
        float k1 = sm[OFF_QKV + (129 + c0) * 65 + pix] * rkp * gk1;
        sm[OFF_QKV + (128 + c0) * 65 + pix] = k0 * cs - k1 * sn;
        sm[OFF_QKV + (129 + c0) * 65 + pix] = k1 * cs + k0 * sn;
    }

    // ---- phase 3.5: w_proj tiles via uint4 copy (phase-1 arena now dead) ----
    #pragma unroll
    for (int t = 0; t < 2; ++t) {
        int w4 = tid + t * 512;
        int row = w4 >> 4, colw = (w4 & 15) * 4;
        *(uint4*)(smc + ARENA_F * 4 + WPH + row * 272 + colw * 4) = pjh[t];
        *(uint4*)(smc + ARENA_F * 4 + WPL + row * 272 + colw * 4) = pjl[t];
    }
    __syncthreads();

    // ---- phase 4: circ conv, f32x2 parity-split ----
    {
        const int cc = tid & 127;
        const int A0 = ((tid >> 7) & 1) * 4;
        const int P  = tid >> 8;
        const float* qb = &sm[OFF_QKV + cc * 65];
        const float* kb = &sm[OFF_QKV + (128 + cc) * 65];
        float v32[32];
        if (P == 0) circ_par<0>(qb, kb, A0, v32);
        else        circ_par<1>(qb, kb, A0, v32);

        float* scratch = (float*)(smc + ARENA_F * 4 + CBH);   // 256 x 33 floats
        int s = tid & 255;
        if (P == 1) {
            #pragma unroll
            for (int t = 0; t < 32; ++t) scratch[s * 33 + t] = v32[t];
        }
        __syncthreads();
        if (P == 0) {
            #pragma unroll
            for (int t = 0; t < 32; ++t) {
                float tot = v32[t] + scratch[s * 33 + t];
                sm[OFF_CORR + cc * 65 + (A0 + (t >> 3)) * 8 + (t & 7)] = tot;
            }
        }
    }
    __syncthreads();

    // ---- phase 5: corr RMS factor (warp -> 4 pixels) ----
    #pragma unroll
    for (int pi = 0; pi < 4; ++pi) {
        int pix = warp * 4 + pi;
        float sc = 0.f;
        #pragma unroll
        for (int r = 0; r < 4; ++r) {
            float cv = sm[OFF_CORR + (lane + r * 32) * 65 + pix];
            sc = fmaf(cv, cv, sc);
        }
        #pragma unroll
        for (int off = 16; off; off >>= 1)
            sc += __shfl_xor_sync(0xffffffffu, sc, off);
        if (lane == 0)
            sm[OFF_RN + pix] = rsqrtf(sc * (1.f / 128.f) + EPSF);
    }
    __syncthreads();

    // ---- phase 6: (v * g_norm * rn * corr) -> bf16 hi/lo B tiles [pix][k] ----
    for (int idx = tid; idx < 64 * 64; idx += 512) {
        int pix = idx >> 6, kp = idx & 63;
        int k0 = 2 * kp;
        float rnp = sm[OFF_RN + pix];
        float c0v = sm[OFF_CORR + k0 * 65 + pix];
        float c1v = sm[OFF_CORR + (k0 + 1) * 65 + pix];
        float v0  = sm[OFF_QKV + (256 + k0) * 65 + pix];
        float v1  = sm[OFF_QKV + (257 + k0) * 65 + pix];
        float w0 = v0 * c0v * rnp * sm[OFF_G + k0];
        float w1 = v1 * c1v * rnp * sm[OFF_G + k0 + 1];
        uint32_t lp, hp = pack_hi_lo(w0, w1, lp);
        *(uint32_t*)(smc + ARENA_F * 4 + CBH + pix * 272 + kp * 4) = hp;
        *(uint32_t*)(smc + ARENA_F * 4 + CBL + pix * 272 + kp * 4) = lp;
    }
    __syncthreads();

    // ---- phase 7: projection HMMA on 16 warps (4 mg x 4 nh, 2 nt each) ----
    {
        const int mg = warp & 3, nh = warp >> 2;
        uint32_t ahw[8][4], alw[8][4];
        const uint32_t aH = arena + WPH + (mg * 16 + (lane & 15)) * 272
                            + (lane >> 4) * 16;
        #pragma unroll
        for (int ks = 0; ks < 8; ++ks) {
            ldsm4(ahw[ks], aH + ks * 32);
            ldsm4(alw[ks], aH + (WPL - WPH) + ks * 32);
        }
        float* ob = out + (size_t)b * 64 * HH * WW;
        #pragma unroll
        for (int t = 0; t < 2; ++t) {
            int nt = nh * 2 + t;
            float acc[4] = {};
            const uint32_t bA = arena + CBH + (nt * 8 + (lane & 7)) * 272
                                + ((lane >> 3) & 1) * 16;
            #pragma unroll
            for (int ks = 0; ks < 8; ++ks) {
                uint32_t bh0, bh1, bl0, bl1;
                ldsm2(bh0, bh1, bA + ks * 32);
                ldsm2(bl0, bl1, bA + (CBL - CBH) + ks * 32);
                mma16816(acc, ahw[ks], bh0, bh1);
                mma16816(acc, ahw[ks], bl0, bl1);
                mma16816(acc, alw[ks], bh0, bh1);
            }
            int o = mg * 16 + (lane >> 2);
            int gy = gy0 + nt;
            int gxp = gx0 + 2 * (lane & 3);
            *(float2*)(ob + (size_t)o * (HH * WW) + gy * WW + gxp)
                = make_float2(acc[0], acc[1]);
            *(float2*)(ob + (size_t)(o + 8) * (HH * WW) + gy * WW + gxp)
                = make_float2(acc[2], acc[3]);
        }
    }
}

extern "C" void kernel_launch(void* const* d_in, const int* in_sizes, int n_in,
                              void* d_out, int out_size)
{
    (void)in_sizes; (void)n_in; (void)out_size;
    const float* x        = (const float*)d_in[0];
    const float* w_hidden = (const float*)d_in[1];
    const float* w_dw     = (const float*)d_in[2];
    const float* w_proj   = (const float*)d_in[3];
    const float* g_norm   = (const float*)d_in[4];
    const float* g_qnorm  = (const float*)d_in[5];
    const float* g_knorm  = (const float*)d_in[6];
    float* out = (float*)d_out;

    prep_weights<<<64, 256>>>(w_hidden, w_proj);

    cudaFuncSetAttribute(fsas_fused_kernel,
                         cudaFuncAttributeMaxDynamicSharedMemorySize, SMEM_BYTES);
    dim3 grid(WW / 8, HH / 8, 4);
    fsas_fused_kernel<<<grid, 512, SMEM_BYTES>>>(
        x, w_dw, g_norm, g_qnorm, g_knorm, out);
}